// round 1
// baseline (speedup 1.0000x reference)
#include <cuda_runtime.h>
#include <cuda_bf16.h>

// Problem constants
#define NN 4
#define QL 64
#define KL 64
#define DD 768
#define HH 16
#define HD 48
#define EE 300
#define NH (NN*HH)   // 64

// Scratch (device globals — no allocation allowed)
__device__ float g_Q[NN*QL*DD];     // [256][768]
__device__ float g_K[KL*DD];        // [64][768]
__device__ float g_V[KL*DD];        // [64][768]
__device__ float g_A[NH*EE*QL];     // [nh][e][q]
__device__ float g_B[NH*KL*QL];     // [nh][k][q]
__device__ float g_W[NH*KL*QL];     // [nh][k][q]

// ---------------------------------------------------------------------------
// Kernel 1: Y[rows x 768] = X[rows x 768] @ Wt[768 x 768] + bias
// BM=64, BN=32, BK=16, 256 threads, 4x2 microtile
// ---------------------------------------------------------------------------
__global__ __launch_bounds__(256) void gemm_bias_kernel(
    const float* __restrict__ X, const float* __restrict__ Wt,
    const float* __restrict__ bias, float* __restrict__ Y, int rows)
{
    __shared__ float As[16][64];   // [k][m] (transposed)
    __shared__ float Bs[16][32];   // [k][c]

    const int tid = threadIdx.x;
    const int m0 = blockIdx.x * 64;
    const int c0 = blockIdx.y * 32;
    const int tx = tid & 15;       // col group (2 cols)
    const int ty = tid >> 4;       // row group (4 rows)

    float acc[4][2];
#pragma unroll
    for (int i = 0; i < 4; i++) { acc[i][0] = 0.f; acc[i][1] = 0.f; }

    for (int k0 = 0; k0 < DD; k0 += 16) {
        // Load A tile: 64 rows x 16 k, float4 per thread
        {
            int r  = tid >> 2;          // 0..63
            int kk = (tid & 3) * 4;     // 0,4,8,12
            float4 a = make_float4(0.f, 0.f, 0.f, 0.f);
            if (m0 + r < rows)
                a = *(const float4*)(X + (size_t)(m0 + r) * DD + k0 + kk);
            As[kk + 0][r] = a.x; As[kk + 1][r] = a.y;
            As[kk + 2][r] = a.z; As[kk + 3][r] = a.w;
        }
        // Load B tile: 16 k x 32 c, float2 per thread
        {
            int kk = tid >> 4;          // 0..15
            int c  = (tid & 15) * 2;
            float2 b = *(const float2*)(Wt + (size_t)(k0 + kk) * DD + c0 + c);
            Bs[kk][c] = b.x; Bs[kk][c + 1] = b.y;
        }
        __syncthreads();
#pragma unroll
        for (int kk = 0; kk < 16; kk++) {
            const float4 a = *(const float4*)&As[kk][ty * 4];
            const float2 b = *(const float2*)&Bs[kk][tx * 2];
            acc[0][0] = fmaf(a.x, b.x, acc[0][0]); acc[0][1] = fmaf(a.x, b.y, acc[0][1]);
            acc[1][0] = fmaf(a.y, b.x, acc[1][0]); acc[1][1] = fmaf(a.y, b.y, acc[1][1]);
            acc[2][0] = fmaf(a.z, b.x, acc[2][0]); acc[2][1] = fmaf(a.z, b.y, acc[2][1]);
            acc[3][0] = fmaf(a.w, b.x, acc[3][0]); acc[3][1] = fmaf(a.w, b.y, acc[3][1]);
        }
        __syncthreads();
    }

    const float b0 = bias[c0 + tx * 2];
    const float b1 = bias[c0 + tx * 2 + 1];
#pragma unroll
    for (int i = 0; i < 4; i++) {
        int r = m0 + ty * 4 + i;
        if (r < rows) {
            Y[(size_t)r * DD + c0 + tx * 2]     = acc[i][0] + b0;
            Y[(size_t)r * DD + c0 + tx * 2 + 1] = acc[i][1] + b1;
        }
    }
}

// ---------------------------------------------------------------------------
// Kernel 2: per (n,h) compute
//   task<5 : A[nh][e][q] = sum_d mem[e,h,d] * Q[n,q,h,d]   (e-tile of 64)
//   task=5 : B[nh][k][q] = sum_d K[k,h,d]  * Q[n,q,h,d]
// 256 threads, 64x64 tile, 4x4 microtile over d=48
// ---------------------------------------------------------------------------
__global__ __launch_bounds__(256) void scores_kernel(
    const float* __restrict__ mem, const float* __restrict__ Q,
    const float* __restrict__ K, float* __restrict__ A, float* __restrict__ B)
{
    const int nh = blockIdx.x;          // 0..63
    const int n = nh >> 4, h = nh & 15;
    const int task = blockIdx.y;        // 0..4 = A e-tiles, 5 = B

    __shared__ float Ls[48][68];        // left rows, transposed [d][r]
    __shared__ float Qs[48][68];        // Q rows, transposed [d][q]

    const int tid = threadIdx.x;

    const float* lbase;
    int R;
    if (task < 5) { lbase = mem + (size_t)task * 64 * DD + h * HD; R = min(64, EE - task * 64); }
    else          { lbase = K + h * HD; R = 64; }

    for (int i = tid; i < 64 * 48; i += 256) {
        int r = i / 48, d = i % 48;
        Ls[d][r] = (r < R) ? lbase[(size_t)r * DD + d] : 0.f;
    }
    const float* qbase = Q + (size_t)n * QL * DD + h * HD;
    for (int i = tid; i < 64 * 48; i += 256) {
        int r = i / 48, d = i % 48;
        Qs[d][r] = qbase[(size_t)r * DD + d];
    }
    __syncthreads();

    const int tx = tid & 15, ty = tid >> 4;
    float acc[4][4];
#pragma unroll
    for (int i = 0; i < 4; i++)
#pragma unroll
        for (int j = 0; j < 4; j++) acc[i][j] = 0.f;

#pragma unroll 8
    for (int d = 0; d < 48; d++) {
        const float4 a = *(const float4*)&Ls[d][ty * 4];
        const float4 b = *(const float4*)&Qs[d][tx * 4];
        acc[0][0] = fmaf(a.x, b.x, acc[0][0]); acc[0][1] = fmaf(a.x, b.y, acc[0][1]);
        acc[0][2] = fmaf(a.x, b.z, acc[0][2]); acc[0][3] = fmaf(a.x, b.w, acc[0][3]);
        acc[1][0] = fmaf(a.y, b.x, acc[1][0]); acc[1][1] = fmaf(a.y, b.y, acc[1][1]);
        acc[1][2] = fmaf(a.y, b.z, acc[1][2]); acc[1][3] = fmaf(a.y, b.w, acc[1][3]);
        acc[2][0] = fmaf(a.z, b.x, acc[2][0]); acc[2][1] = fmaf(a.z, b.y, acc[2][1]);
        acc[2][2] = fmaf(a.z, b.z, acc[2][2]); acc[2][3] = fmaf(a.z, b.w, acc[2][3]);
        acc[3][0] = fmaf(a.w, b.x, acc[3][0]); acc[3][1] = fmaf(a.w, b.y, acc[3][1]);
        acc[3][2] = fmaf(a.w, b.z, acc[3][2]); acc[3][3] = fmaf(a.w, b.w, acc[3][3]);
    }

    if (task < 5) {
        float* out = A + (size_t)nh * EE * QL;
#pragma unroll
        for (int i = 0; i < 4; i++) {
            int e = task * 64 + ty * 4 + i;
            if (e < EE) {
#pragma unroll
                for (int j = 0; j < 4; j++)
                    out[(size_t)e * QL + tx * 4 + j] = acc[i][j];
            }
        }
    } else {
        float* out = B + (size_t)nh * KL * QL;
#pragma unroll
        for (int i = 0; i < 4; i++)
#pragma unroll
            for (int j = 0; j < 4; j++)
                out[(size_t)(ty * 4 + i) * QL + tx * 4 + j] = acc[i][j];
    }
}

// ---------------------------------------------------------------------------
// Kernel 3: W[nh][k][q] = sum_e relu(A[e,q]+B[k,q]) * (sum_q' relu(A[e,q']+B[k,q']))
// grid (64 nh, 8 k-groups), 8 warps/block, warp owns one k, lanes own q / q+32
// ---------------------------------------------------------------------------
__global__ __launch_bounds__(256) void wk_kernel(
    const float* __restrict__ A, const float* __restrict__ B, float* __restrict__ W)
{
    const int nh   = blockIdx.x;
    const int warp = threadIdx.x >> 5;
    const int lane = threadIdx.x & 31;
    const int k    = blockIdx.y * 8 + warp;

    const float* Bk = B + (size_t)nh * KL * QL + (size_t)k * QL;
    const float b0 = Bk[lane];
    const float b1 = Bk[lane + 32];
    const float* Ab = A + (size_t)nh * EE * QL;

    float w0 = 0.f, w1 = 0.f;
#pragma unroll 4
    for (int e = 0; e < EE; e++) {
        const float a0 = __ldg(Ab + (size_t)e * QL + lane);
        const float a1 = __ldg(Ab + (size_t)e * QL + lane + 32);
        const float s0 = fmaxf(a0 + b0, 0.f);
        const float s1 = fmaxf(a1 + b1, 0.f);
        float t = s0 + s1;
#pragma unroll
        for (int o = 16; o > 0; o >>= 1)
            t += __shfl_xor_sync(0xffffffffu, t, o);
        w0 = fmaf(t, s0, w0);
        w1 = fmaf(t, s1, w1);
    }
    float* Wk = W + (size_t)nh * KL * QL + (size_t)k * QL;
    Wk[lane]      = w0;
    Wk[lane + 32] = w1;
}

// ---------------------------------------------------------------------------
// Kernel 4: out[n,q,h,d] = sum_k W[nh][k][q] * V[k,h,d]
// block per (n,h), 256 threads, smem-resident W (16KB) + V_h (12KB)
// ---------------------------------------------------------------------------
__global__ __launch_bounds__(256) void out_kernel(
    const float* __restrict__ W, const float* __restrict__ V, float* __restrict__ out)
{
    const int nh = blockIdx.x;
    const int n = nh >> 4, h = nh & 15;

    __shared__ float Ws[64][64];   // [k][q]
    __shared__ float Vs[64][48];   // [k][d]

    const int tid = threadIdx.x;
    const float* Wb = W + (size_t)nh * KL * QL;
    for (int i = tid; i < 64 * 64; i += 256)
        Ws[i >> 6][i & 63] = Wb[i];
    for (int i = tid; i < 64 * 48; i += 256) {
        int kk = i / 48, d = i % 48;
        Vs[kk][d] = V[(size_t)kk * DD + h * HD + d];
    }
    __syncthreads();

    const int tx = tid & 15;      // d group of 3
    const int ty = tid >> 4;      // q group of 4
    float acc[4][3];
#pragma unroll
    for (int i = 0; i < 4; i++)
#pragma unroll
        for (int j = 0; j < 3; j++) acc[i][j] = 0.f;

#pragma unroll 4
    for (int kk = 0; kk < 64; kk++) {
        float wq[4], vd[3];
#pragma unroll
        for (int i = 0; i < 4; i++) wq[i] = Ws[kk][ty * 4 + i];
#pragma unroll
        for (int j = 0; j < 3; j++) vd[j] = Vs[kk][tx * 3 + j];
#pragma unroll
        for (int i = 0; i < 4; i++)
#pragma unroll
            for (int j = 0; j < 3; j++)
                acc[i][j] = fmaf(wq[i], vd[j], acc[i][j]);
    }

#pragma unroll
    for (int i = 0; i < 4; i++) {
        int q = ty * 4 + i;
#pragma unroll
        for (int j = 0; j < 3; j++) {
            int d = tx * 3 + j;
            out[(size_t)(n * QL + q) * DD + h * HD + d] = acc[i][j];
        }
    }
}

// ---------------------------------------------------------------------------
// Launch
// Inputs: 0=q 1=k 2=v 3=Wq 4=bq 5=Wk 6=bk 7=Wv 8=bv 9=memory
// ---------------------------------------------------------------------------
extern "C" void kernel_launch(void* const* d_in, const int* in_sizes, int n_in,
                              void* d_out, int out_size)
{
    const float* q   = (const float*)d_in[0];
    const float* k   = (const float*)d_in[1];
    const float* v   = (const float*)d_in[2];
    const float* Wq  = (const float*)d_in[3];
    const float* bq  = (const float*)d_in[4];
    const float* Wk  = (const float*)d_in[5];
    const float* bk  = (const float*)d_in[6];
    const float* Wv  = (const float*)d_in[7];
    const float* bv  = (const float*)d_in[8];
    const float* mem = (const float*)d_in[9];
    float* out = (float*)d_out;

    float *gQ, *gK, *gV, *gA, *gB, *gW;
    cudaGetSymbolAddress((void**)&gQ, g_Q);
    cudaGetSymbolAddress((void**)&gK, g_K);
    cudaGetSymbolAddress((void**)&gV, g_V);
    cudaGetSymbolAddress((void**)&gA, g_A);
    cudaGetSymbolAddress((void**)&gB, g_B);
    cudaGetSymbolAddress((void**)&gW, g_W);

    // 1. Projections
    gemm_bias_kernel<<<dim3(4, 24), 256>>>(q, Wq, bq, gQ, NN * QL);
    gemm_bias_kernel<<<dim3(1, 24), 256>>>(k, Wk, bk, gK, KL);
    gemm_bias_kernel<<<dim3(1, 24), 256>>>(v, Wv, bv, gV, KL);

    // 2. A (mem·Q) and B (K·Q) scores per (n,h)
    scores_kernel<<<dim3(NH, 6), 256>>>(mem, gQ, gK, gA, gB);

    // 3. W[nh][k][q]
    wk_kernel<<<dim3(NH, 8), 256>>>(gA, gB, gW);

    // 4. out = W^T @ V_h per (n,h)
    out_kernel<<<NH, 256>>>(gW, gV, out);
}

// round 3
// speedup vs baseline: 1.3141x; 1.3141x over previous
#include <cuda_runtime.h>
#include <cuda_bf16.h>

// Problem constants
#define NN 4
#define QL 64
#define KL 64
#define DD 768
#define HH 16
#define HD 48
#define EE 300
#define NH (NN*HH)   // 64

// Scratch (device globals — no allocation allowed). 128B-aligned for float4 access.
__device__ __align__(128) float g_Q[NN*QL*DD];     // [256][768]
__device__ __align__(128) float g_K[KL*DD];        // [64][768]
__device__ __align__(128) float g_V[KL*DD];        // [64][768]
__device__ __align__(128) float g_A[NH*EE*QL];     // [nh][e][q]
__device__ __align__(128) float g_B[NH*KL*QL];     // [nh][k][q]
__device__ __align__(128) float g_T[NH*EE*KL];     // [nh][e][k]
__device__ __align__(128) float g_W[NH*KL*QL];     // [nh][k][q]

// ---------------------------------------------------------------------------
// Kernel 1: fused Q/K/V projections. Y = X @ Wt + bias
// grid (6 row-tiles, 24 col-tiles): rt 0-3 = Q tiles, 4 = K, 5 = V
// BM=64, BN=32, BK=32, 256 threads, 4x2 microtile. One full wave.
// ---------------------------------------------------------------------------
__global__ __launch_bounds__(256) void proj_kernel(
    const float* __restrict__ qin, const float* __restrict__ kin,
    const float* __restrict__ vin,
    const float* __restrict__ Wq, const float* __restrict__ Wk,
    const float* __restrict__ Wv,
    const float* __restrict__ bq, const float* __restrict__ bk,
    const float* __restrict__ bv,
    float* __restrict__ Qo, float* __restrict__ Ko, float* __restrict__ Vo)
{
    __shared__ float As[32][64];   // [k][m] transposed (256B rows, float4-safe)
    __shared__ float Bs[32][34];   // [k][c] (136B rows, float2-safe)

    const int rt = blockIdx.x;
    const int c0 = blockIdx.y * 32;
    const float *X, *Wt, *bias;
    float* Y;
    if (rt < 4)      { X = qin + (size_t)rt * 64 * DD; Wt = Wq; bias = bq; Y = Qo + (size_t)rt * 64 * DD; }
    else if (rt == 4){ X = kin; Wt = Wk; bias = bk; Y = Ko; }
    else             { X = vin; Wt = Wv; bias = bv; Y = Vo; }

    const int tid = threadIdx.x;
    const int tx = tid & 15;       // col group (2 cols)
    const int ty = tid >> 4;       // row group (4 rows)
    const int lr = tid >> 2;       // A load row 0..63
    const int lc = (tid & 3) * 4;  // A load k-offset (and +16)
    const int br = tid >> 3;       // B load k-row 0..31
    const int bc = (tid & 7) * 4;  // B load col

    float acc[4][2];
#pragma unroll
    for (int i = 0; i < 4; i++) { acc[i][0] = 0.f; acc[i][1] = 0.f; }

    for (int k0 = 0; k0 < DD; k0 += 32) {
        const float4 a0 = *(const float4*)(X + (size_t)lr * DD + k0 + lc);
        const float4 a1 = *(const float4*)(X + (size_t)lr * DD + k0 + lc + 16);
        const float4 bb = *(const float4*)(Wt + (size_t)(k0 + br) * DD + c0 + bc);
        As[lc + 0][lr] = a0.x; As[lc + 1][lr] = a0.y;
        As[lc + 2][lr] = a0.z; As[lc + 3][lr] = a0.w;
        As[lc + 16][lr] = a1.x; As[lc + 17][lr] = a1.y;
        As[lc + 18][lr] = a1.z; As[lc + 19][lr] = a1.w;
        Bs[br][bc + 0] = bb.x; Bs[br][bc + 1] = bb.y;
        Bs[br][bc + 2] = bb.z; Bs[br][bc + 3] = bb.w;
        __syncthreads();
#pragma unroll
        for (int kk = 0; kk < 32; kk++) {
            const float4 a = *(const float4*)&As[kk][ty * 4];
            const float2 b = *(const float2*)&Bs[kk][tx * 2];
            acc[0][0] = fmaf(a.x, b.x, acc[0][0]); acc[0][1] = fmaf(a.x, b.y, acc[0][1]);
            acc[1][0] = fmaf(a.y, b.x, acc[1][0]); acc[1][1] = fmaf(a.y, b.y, acc[1][1]);
            acc[2][0] = fmaf(a.z, b.x, acc[2][0]); acc[2][1] = fmaf(a.z, b.y, acc[2][1]);
            acc[3][0] = fmaf(a.w, b.x, acc[3][0]); acc[3][1] = fmaf(a.w, b.y, acc[3][1]);
        }
        __syncthreads();
    }

    const float b0 = bias[c0 + tx * 2];
    const float b1 = bias[c0 + tx * 2 + 1];
#pragma unroll
    for (int i = 0; i < 4; i++) {
        float2 o = make_float2(acc[i][0] + b0, acc[i][1] + b1);
        *(float2*)(Y + (size_t)(ty * 4 + i) * DD + c0 + tx * 2) = o;
    }
}

// ---------------------------------------------------------------------------
// Kernel 2: per (n,h) scores
//   task<5 : A[nh][e][q] = sum_d mem[e,h,d] * Q[n,q,h,d]   (e-tile of 64)
//   task=5 : B[nh][k][q] = sum_d K[k,h,d]  * Q[n,q,h,d]
// 68-float row stride = 272B = 17*16 -> float4-safe.
// ---------------------------------------------------------------------------
__global__ __launch_bounds__(256) void scores_kernel(
    const float* __restrict__ mem, const float* __restrict__ Q,
    const float* __restrict__ K, float* __restrict__ A, float* __restrict__ B)
{
    const int nh = blockIdx.x;          // 0..63
    const int n = nh >> 4, h = nh & 15;
    const int task = blockIdx.y;        // 0..4 = A e-tiles, 5 = B

    __shared__ float Ls[48][68];        // [d][r]
    __shared__ float Qs[48][68];        // [d][q]

    const int tid = threadIdx.x;
    const int r = tid >> 2;             // 0..63
    const int c = tid & 3;

    const float* lbase;
    int R;
    if (task < 5) { lbase = mem + (size_t)task * 64 * DD + h * HD; R = min(64, EE - task * 64); }
    else          { lbase = K + h * HD; R = 64; }

    {
        const float* srcL = lbase + (size_t)r * DD;
        const float* srcQ = Q + (size_t)(n * QL + r) * DD + h * HD;
#pragma unroll
        for (int j = 0; j < 3; j++) {
            const int d0 = c * 4 + j * 16;
            float4 vl = make_float4(0.f, 0.f, 0.f, 0.f);
            if (r < R) vl = *(const float4*)(srcL + d0);
            Ls[d0 + 0][r] = vl.x; Ls[d0 + 1][r] = vl.y;
            Ls[d0 + 2][r] = vl.z; Ls[d0 + 3][r] = vl.w;
            const float4 vq = *(const float4*)(srcQ + d0);
            Qs[d0 + 0][r] = vq.x; Qs[d0 + 1][r] = vq.y;
            Qs[d0 + 2][r] = vq.z; Qs[d0 + 3][r] = vq.w;
        }
    }
    __syncthreads();

    const int tx = tid & 15, ty = tid >> 4;
    float acc[4][4];
#pragma unroll
    for (int i = 0; i < 4; i++)
#pragma unroll
        for (int j = 0; j < 4; j++) acc[i][j] = 0.f;

#pragma unroll 8
    for (int d = 0; d < 48; d++) {
        const float4 a = *(const float4*)&Ls[d][ty * 4];
        const float4 b = *(const float4*)&Qs[d][tx * 4];
        acc[0][0] = fmaf(a.x, b.x, acc[0][0]); acc[0][1] = fmaf(a.x, b.y, acc[0][1]);
        acc[0][2] = fmaf(a.x, b.z, acc[0][2]); acc[0][3] = fmaf(a.x, b.w, acc[0][3]);
        acc[1][0] = fmaf(a.y, b.x, acc[1][0]); acc[1][1] = fmaf(a.y, b.y, acc[1][1]);
        acc[1][2] = fmaf(a.y, b.z, acc[1][2]); acc[1][3] = fmaf(a.y, b.w, acc[1][3]);
        acc[2][0] = fmaf(a.z, b.x, acc[2][0]); acc[2][1] = fmaf(a.z, b.y, acc[2][1]);
        acc[2][2] = fmaf(a.z, b.z, acc[2][2]); acc[2][3] = fmaf(a.z, b.w, acc[2][3]);
        acc[3][0] = fmaf(a.w, b.x, acc[3][0]); acc[3][1] = fmaf(a.w, b.y, acc[3][1]);
        acc[3][2] = fmaf(a.w, b.z, acc[3][2]); acc[3][3] = fmaf(a.w, b.w, acc[3][3]);
    }

    if (task < 5) {
        float* out = A + (size_t)nh * EE * QL;
#pragma unroll
        for (int i = 0; i < 4; i++) {
            int e = task * 64 + ty * 4 + i;
            if (e < EE) {
                float4 o = make_float4(acc[i][0], acc[i][1], acc[i][2], acc[i][3]);
                *(float4*)(out + (size_t)e * QL + tx * 4) = o;
            }
        }
    } else {
        float* out = B + (size_t)nh * KL * QL;
#pragma unroll
        for (int i = 0; i < 4; i++) {
            float4 o = make_float4(acc[i][0], acc[i][1], acc[i][2], acc[i][3]);
            *(float4*)(out + (size_t)(ty * 4 + i) * QL + tx * 4) = o;
        }
    }
}

// ---------------------------------------------------------------------------
// Kernel 3a: T[nh][e][k] = sum_q relu(A[nh][e][q] + B[nh][k][q])
// grid (64, 10 e-tiles of 32), 256 threads. No cross-lane reduce.
// ---------------------------------------------------------------------------
__global__ __launch_bounds__(256) void tsum_kernel(
    const float* __restrict__ A, const float* __restrict__ B, float* __restrict__ T)
{
    const int nh = blockIdx.x;
    const int e0 = blockIdx.y * 32;
    const int ecount = min(32, EE - e0);

    __shared__ float Ash[32][64];       // [e][q] (256B rows)
    __shared__ float Bsh[64][66];       // [k][q] (264B rows, float2-safe)

    const int tid = threadIdx.x;
    const float* Ab = A + ((size_t)nh * EE + e0) * QL;
#pragma unroll
    for (int i = 0; i < 2; i++) {
        int f = tid + i * 256;          // float4 index
        int e = f >> 4, qq = (f & 15) * 4;
        float4 v = make_float4(0.f, 0.f, 0.f, 0.f);
        if (e < ecount) v = *(const float4*)(Ab + (size_t)e * QL + qq);
        *(float4*)&Ash[e][qq] = v;
    }
    const float* Bb = B + (size_t)nh * KL * QL;
#pragma unroll
    for (int i = 0; i < 4; i++) {
        int f = tid + i * 256;
        int k = f >> 4, qq = (f & 15) * 4;
        float4 v = *(const float4*)(Bb + (size_t)k * QL + qq);
        Bsh[k][qq + 0] = v.x; Bsh[k][qq + 1] = v.y;
        Bsh[k][qq + 2] = v.z; Bsh[k][qq + 3] = v.w;
    }
    __syncthreads();

    const int k = tid & 63;
    const int ebase = tid >> 6;         // 0..3

    float sx[8], sy[8];
#pragma unroll
    for (int i = 0; i < 8; i++) { sx[i] = 0.f; sy[i] = 0.f; }

#pragma unroll 4
    for (int q2 = 0; q2 < 32; q2++) {
        const float2 b = *(const float2*)&Bsh[k][q2 * 2];
#pragma unroll
        for (int i = 0; i < 8; i++) {
            const int e = ebase + i * 4;
            const float2 a = *(const float2*)&Ash[e][q2 * 2];
            sx[i] += fmaxf(a.x + b.x, 0.f);
            sy[i] += fmaxf(a.y + b.y, 0.f);
        }
    }

    float* Tb = T + ((size_t)nh * EE + e0) * KL;
#pragma unroll
    for (int i = 0; i < 8; i++) {
        const int e = ebase + i * 4;
        if (e < ecount)
            Tb[(size_t)e * KL + k] = sx[i] + sy[i];
    }
}

// ---------------------------------------------------------------------------
// Kernel 3b: W[nh][k][q] = sum_e relu(A[e,q]+B[k,q]) * T[e,k]
// grid (64 nh, 4 k-groups of 16), 256 threads.
// ---------------------------------------------------------------------------
__global__ __launch_bounds__(256) void wk_kernel(
    const float* __restrict__ A, const float* __restrict__ B,
    const float* __restrict__ T, float* __restrict__ W)
{
    const int nh = blockIdx.x;
    const int kg = blockIdx.y;

    __shared__ float Ash[64][64];       // [e][q] tile (256B rows)
    __shared__ float Tsh[64][16];       // [e][k-local]

    const int tid = threadIdx.x;
    const int q2 = tid & 31;
    const int kl0 = tid >> 5;           // 0..7
    const int k0 = kg * 16 + kl0;
    const int k1 = k0 + 8;

    const float* Bb = B + (size_t)nh * KL * QL;
    const float2 b0 = *(const float2*)(Bb + (size_t)k0 * QL + q2 * 2);
    const float2 b1 = *(const float2*)(Bb + (size_t)k1 * QL + q2 * 2);

    float2 w0 = make_float2(0.f, 0.f);
    float2 w1 = make_float2(0.f, 0.f);

    const float* Ab = A + (size_t)nh * EE * QL;
    const float* Tb = T + (size_t)nh * EE * KL + kg * 16;

    for (int et = 0; et < 5; et++) {
        const int e0 = et * 64;
        const int ec = min(64, EE - e0);
#pragma unroll
        for (int i = 0; i < 4; i++) {
            int f = tid + i * 256;
            int e = f >> 4, qq = (f & 15) * 4;
            float4 v = make_float4(0.f, 0.f, 0.f, 0.f);
            if (e < ec) v = *(const float4*)(Ab + (size_t)(e0 + e) * QL + qq);
            *(float4*)&Ash[e][qq] = v;
        }
#pragma unroll
        for (int i = 0; i < 4; i++) {
            int f = tid + i * 256;
            int e = f >> 4, kk = f & 15;
            float v = 0.f;
            if (e < ec) v = Tb[(size_t)(e0 + e) * KL + kk];
            Tsh[e][kk] = v;
        }
        __syncthreads();

#pragma unroll 4
        for (int e = 0; e < 64; e++) {
            const float2 a = *(const float2*)&Ash[e][q2 * 2];
            const float t0 = Tsh[e][kl0];
            const float t1 = Tsh[e][kl0 + 8];
            float s;
            s = fmaxf(a.x + b0.x, 0.f); w0.x = fmaf(t0, s, w0.x);
            s = fmaxf(a.y + b0.y, 0.f); w0.y = fmaf(t0, s, w0.y);
            s = fmaxf(a.x + b1.x, 0.f); w1.x = fmaf(t1, s, w1.x);
            s = fmaxf(a.y + b1.y, 0.f); w1.y = fmaf(t1, s, w1.y);
        }
        __syncthreads();
    }

    float* Wb = W + (size_t)nh * KL * QL;
    *(float2*)(Wb + (size_t)k0 * QL + q2 * 2) = w0;
    *(float2*)(Wb + (size_t)k1 * QL + q2 * 2) = w1;
}

// ---------------------------------------------------------------------------
// Kernel 4: out[n,q,h,d] = sum_k W[nh][k][q] * V[k,h,d]
// ---------------------------------------------------------------------------
__global__ __launch_bounds__(256) void out_kernel(
    const float* __restrict__ W, const float* __restrict__ V, float* __restrict__ out)
{
    const int nh = blockIdx.x;
    const int n = nh >> 4, h = nh & 15;

    __shared__ float Ws[64][64];   // [k][q]
    __shared__ float Vs[64][48];   // [k][d]

    const int tid = threadIdx.x;
    const float* Wb = W + (size_t)nh * KL * QL;
    for (int i = tid; i < 64 * 64; i += 256)
        Ws[i >> 6][i & 63] = Wb[i];
    for (int i = tid; i < 64 * 48; i += 256) {
        int kk = i / 48, d = i % 48;
        Vs[kk][d] = V[(size_t)kk * DD + h * HD + d];
    }
    __syncthreads();

    const int tx = tid & 15;      // d group of 3
    const int ty = tid >> 4;      // q group of 4
    float acc[4][3];
#pragma unroll
    for (int i = 0; i < 4; i++)
#pragma unroll
        for (int j = 0; j < 3; j++) acc[i][j] = 0.f;

#pragma unroll 4
    for (int kk = 0; kk < 64; kk++) {
        float wq[4], vd[3];
#pragma unroll
        for (int i = 0; i < 4; i++) wq[i] = Ws[kk][ty * 4 + i];
#pragma unroll
        for (int j = 0; j < 3; j++) vd[j] = Vs[kk][tx * 3 + j];
#pragma unroll
        for (int i = 0; i < 4; i++)
#pragma unroll
            for (int j = 0; j < 3; j++)
                acc[i][j] = fmaf(wq[i], vd[j], acc[i][j]);
    }

#pragma unroll
    for (int i = 0; i < 4; i++) {
        int q = ty * 4 + i;
#pragma unroll
        for (int j = 0; j < 3; j++) {
            int d = tx * 3 + j;
            out[(size_t)(n * QL + q) * DD + h * HD + d] = acc[i][j];
        }
    }
}

// ---------------------------------------------------------------------------
// Launch
// Inputs: 0=q 1=k 2=v 3=Wq 4=bq 5=Wk 6=bk 7=Wv 8=bv 9=memory
// ---------------------------------------------------------------------------
extern "C" void kernel_launch(void* const* d_in, const int* in_sizes, int n_in,
                              void* d_out, int out_size)
{
    const float* q   = (const float*)d_in[0];
    const float* k   = (const float*)d_in[1];
    const float* v   = (const float*)d_in[2];
    const float* Wq  = (const float*)d_in[3];
    const float* bq  = (const float*)d_in[4];
    const float* Wk  = (const float*)d_in[5];
    const float* bk  = (const float*)d_in[6];
    const float* Wv  = (const float*)d_in[7];
    const float* bv  = (const float*)d_in[8];
    const float* mem = (const float*)d_in[9];
    float* out = (float*)d_out;

    float *gQ, *gK, *gV, *gA, *gB, *gT, *gW;
    cudaGetSymbolAddress((void**)&gQ, g_Q);
    cudaGetSymbolAddress((void**)&gK, g_K);
    cudaGetSymbolAddress((void**)&gV, g_V);
    cudaGetSymbolAddress((void**)&gA, g_A);
    cudaGetSymbolAddress((void**)&gB, g_B);
    cudaGetSymbolAddress((void**)&gT, g_T);
    cudaGetSymbolAddress((void**)&gW, g_W);

    // 1. Fused projections (one wave)
    proj_kernel<<<dim3(6, 24), 256>>>(q, k, v, Wq, Wk, Wv, bq, bk, bv, gQ, gK, gV);

    // 2. A (mem·Q) and B (K·Q) scores
    scores_kernel<<<dim3(NH, 6), 256>>>(mem, gQ, gK, gA, gB);

    // 3a. T[e,k] row sums (shuffle-free)
    tsum_kernel<<<dim3(NH, 10), 256>>>(gA, gB, gT);

    // 3b. W[k,q]
    wk_kernel<<<dim3(NH, 4), 256>>>(gA, gB, gT, gW);

    // 4. out = W^T @ V_h
    out_kernel<<<NH, 256>>>(gW, gV, out);
}

// round 4
// speedup vs baseline: 2.0316x; 1.5460x over previous
#include <cuda_runtime.h>
#include <cuda_bf16.h>

// Problem constants
#define NN 4
#define QL 64
#define KL 64
#define DD 768
#define HH 16
#define HD 48
#define EE 300
#define NH (NN*HH)   // 64

// Scratch (device globals — no allocation allowed). 128B-aligned for float4 access.
__device__ __align__(128) float g_Q[NN*QL*DD];     // [256][768]
__device__ __align__(128) float g_K[KL*DD];        // [64][768]
__device__ __align__(128) float g_V[KL*DD];        // [64][768]
__device__ __align__(128) float g_A[NH*EE*QL];     // [nh][e][q]
__device__ __align__(128) float g_B[NH*KL*QL];     // [nh][k][q]
__device__ __align__(128) float g_T[NH*EE*KL];     // [nh][e][k]
__device__ __align__(128) float g_W[NH*KL*QL];     // [nh][k][q]

// ---------------------------------------------------------------------------
// Kernel 1: fused Q/K/V projections. Y = X @ Wt + bias
// grid (6 row-tiles, 24 col-tiles): rt 0-3 = Q tiles, 4 = K, 5 = V
// ---------------------------------------------------------------------------
__global__ __launch_bounds__(256) void proj_kernel(
    const float* __restrict__ qin, const float* __restrict__ kin,
    const float* __restrict__ vin,
    const float* __restrict__ Wq, const float* __restrict__ Wk,
    const float* __restrict__ Wv,
    const float* __restrict__ bq, const float* __restrict__ bk,
    const float* __restrict__ bv,
    float* __restrict__ Qo, float* __restrict__ Ko, float* __restrict__ Vo)
{
    __shared__ float As[32][64];   // [k][m] transposed (256B rows, float4-safe)
    __shared__ float Bs[32][34];   // [k][c] (136B rows, float2-safe)

    const int rt = blockIdx.x;
    const int c0 = blockIdx.y * 32;
    const float *X, *Wt, *bias;
    float* Y;
    if (rt < 4)      { X = qin + (size_t)rt * 64 * DD; Wt = Wq; bias = bq; Y = Qo + (size_t)rt * 64 * DD; }
    else if (rt == 4){ X = kin; Wt = Wk; bias = bk; Y = Ko; }
    else             { X = vin; Wt = Wv; bias = bv; Y = Vo; }

    const int tid = threadIdx.x;
    const int tx = tid & 15;       // col group (2 cols)
    const int ty = tid >> 4;       // row group (4 rows)
    const int lr = tid >> 2;       // A load row 0..63
    const int lc = (tid & 3) * 4;  // A load k-offset (and +16)
    const int br = tid >> 3;       // B load k-row 0..31
    const int bc = (tid & 7) * 4;  // B load col

    float acc[4][2];
#pragma unroll
    for (int i = 0; i < 4; i++) { acc[i][0] = 0.f; acc[i][1] = 0.f; }

    for (int k0 = 0; k0 < DD; k0 += 32) {
        const float4 a0 = *(const float4*)(X + (size_t)lr * DD + k0 + lc);
        const float4 a1 = *(const float4*)(X + (size_t)lr * DD + k0 + lc + 16);
        const float4 bb = *(const float4*)(Wt + (size_t)(k0 + br) * DD + c0 + bc);
        As[lc + 0][lr] = a0.x; As[lc + 1][lr] = a0.y;
        As[lc + 2][lr] = a0.z; As[lc + 3][lr] = a0.w;
        As[lc + 16][lr] = a1.x; As[lc + 17][lr] = a1.y;
        As[lc + 18][lr] = a1.z; As[lc + 19][lr] = a1.w;
        Bs[br][bc + 0] = bb.x; Bs[br][bc + 1] = bb.y;
        Bs[br][bc + 2] = bb.z; Bs[br][bc + 3] = bb.w;
        __syncthreads();
#pragma unroll
        for (int kk = 0; kk < 32; kk++) {
            const float4 a = *(const float4*)&As[kk][ty * 4];
            const float2 b = *(const float2*)&Bs[kk][tx * 2];
            acc[0][0] = fmaf(a.x, b.x, acc[0][0]); acc[0][1] = fmaf(a.x, b.y, acc[0][1]);
            acc[1][0] = fmaf(a.y, b.x, acc[1][0]); acc[1][1] = fmaf(a.y, b.y, acc[1][1]);
            acc[2][0] = fmaf(a.z, b.x, acc[2][0]); acc[2][1] = fmaf(a.z, b.y, acc[2][1]);
            acc[3][0] = fmaf(a.w, b.x, acc[3][0]); acc[3][1] = fmaf(a.w, b.y, acc[3][1]);
        }
        __syncthreads();
    }

    const float b0 = bias[c0 + tx * 2];
    const float b1 = bias[c0 + tx * 2 + 1];
#pragma unroll
    for (int i = 0; i < 4; i++) {
        float2 o = make_float2(acc[i][0] + b0, acc[i][1] + b1);
        *(float2*)(Y + (size_t)(ty * 4 + i) * DD + c0 + tx * 2) = o;
    }
}

// ---------------------------------------------------------------------------
// Kernel 2: per (n,h) scores
//   task<5 : A[nh][e][q] = sum_d mem[e,h,d] * Q[n,q,h,d]   (e-tile of 64)
//   task=5 : B[nh][k][q] = sum_d K[k,h,d]  * Q[n,q,h,d]
// ---------------------------------------------------------------------------
__global__ __launch_bounds__(256) void scores_kernel(
    const float* __restrict__ mem, const float* __restrict__ Q,
    const float* __restrict__ K, float* __restrict__ A, float* __restrict__ B)
{
    const int nh = blockIdx.x;          // 0..63
    const int n = nh >> 4, h = nh & 15;
    const int task = blockIdx.y;        // 0..4 = A e-tiles, 5 = B

    __shared__ float Ls[48][68];        // [d][r] (272B rows, float4-safe)
    __shared__ float Qs[48][68];        // [d][q]

    const int tid = threadIdx.x;
    const int r = tid >> 2;             // 0..63
    const int c = tid & 3;

    const float* lbase;
    int R;
    if (task < 5) { lbase = mem + (size_t)task * 64 * DD + h * HD; R = min(64, EE - task * 64); }
    else          { lbase = K + h * HD; R = 64; }

    {
        const float* srcL = lbase + (size_t)r * DD;
        const float* srcQ = Q + (size_t)(n * QL + r) * DD + h * HD;
#pragma unroll
        for (int j = 0; j < 3; j++) {
            const int d0 = c * 4 + j * 16;
            float4 vl = make_float4(0.f, 0.f, 0.f, 0.f);
            if (r < R) vl = *(const float4*)(srcL + d0);
            Ls[d0 + 0][r] = vl.x; Ls[d0 + 1][r] = vl.y;
            Ls[d0 + 2][r] = vl.z; Ls[d0 + 3][r] = vl.w;
            const float4 vq = *(const float4*)(srcQ + d0);
            Qs[d0 + 0][r] = vq.x; Qs[d0 + 1][r] = vq.y;
            Qs[d0 + 2][r] = vq.z; Qs[d0 + 3][r] = vq.w;
        }
    }
    __syncthreads();

    const int tx = tid & 15, ty = tid >> 4;
    float acc[4][4];
#pragma unroll
    for (int i = 0; i < 4; i++)
#pragma unroll
        for (int j = 0; j < 4; j++) acc[i][j] = 0.f;

#pragma unroll 8
    for (int d = 0; d < 48; d++) {
        const float4 a = *(const float4*)&Ls[d][ty * 4];
        const float4 b = *(const float4*)&Qs[d][tx * 4];
        acc[0][0] = fmaf(a.x, b.x, acc[0][0]); acc[0][1] = fmaf(a.x, b.y, acc[0][1]);
        acc[0][2] = fmaf(a.x, b.z, acc[0][2]); acc[0][3] = fmaf(a.x, b.w, acc[0][3]);
        acc[1][0] = fmaf(a.y, b.x, acc[1][0]); acc[1][1] = fmaf(a.y, b.y, acc[1][1]);
        acc[1][2] = fmaf(a.y, b.z, acc[1][2]); acc[1][3] = fmaf(a.y, b.w, acc[1][3]);
        acc[2][0] = fmaf(a.z, b.x, acc[2][0]); acc[2][1] = fmaf(a.z, b.y, acc[2][1]);
        acc[2][2] = fmaf(a.z, b.z, acc[2][2]); acc[2][3] = fmaf(a.z, b.w, acc[2][3]);
        acc[3][0] = fmaf(a.w, b.x, acc[3][0]); acc[3][1] = fmaf(a.w, b.y, acc[3][1]);
        acc[3][2] = fmaf(a.w, b.z, acc[3][2]); acc[3][3] = fmaf(a.w, b.w, acc[3][3]);
    }

    if (task < 5) {
        float* out = A + (size_t)nh * EE * QL;
#pragma unroll
        for (int i = 0; i < 4; i++) {
            int e = task * 64 + ty * 4 + i;
            if (e < EE) {
                float4 o = make_float4(acc[i][0], acc[i][1], acc[i][2], acc[i][3]);
                *(float4*)(out + (size_t)e * QL + tx * 4) = o;
            }
        }
    } else {
        float* out = B + (size_t)nh * KL * QL;
#pragma unroll
        for (int i = 0; i < 4; i++) {
            float4 o = make_float4(acc[i][0], acc[i][1], acc[i][2], acc[i][3]);
            *(float4*)(out + (size_t)(ty * 4 + i) * QL + tx * 4) = o;
        }
    }
}

// ---------------------------------------------------------------------------
// Kernel 3a: T[nh][e][k] = sum_q relu(A[nh][e][q] + B[nh][k][q])
// grid (64, 10 e-tiles of 32), 256 threads. Already near fma floor; unchanged.
// ---------------------------------------------------------------------------
__global__ __launch_bounds__(256) void tsum_kernel(
    const float* __restrict__ A, const float* __restrict__ B, float* __restrict__ T)
{
    const int nh = blockIdx.x;
    const int e0 = blockIdx.y * 32;
    const int ecount = min(32, EE - e0);

    __shared__ float Ash[32][64];       // [e][q] (256B rows)
    __shared__ float Bsh[64][66];       // [k][q] (264B rows, float2-safe)

    const int tid = threadIdx.x;
    const float* Ab = A + ((size_t)nh * EE + e0) * QL;
#pragma unroll
    for (int i = 0; i < 2; i++) {
        int f = tid + i * 256;          // float4 index
        int e = f >> 4, qq = (f & 15) * 4;
        float4 v = make_float4(0.f, 0.f, 0.f, 0.f);
        if (e < ecount) v = *(const float4*)(Ab + (size_t)e * QL + qq);
        *(float4*)&Ash[e][qq] = v;
    }
    const float* Bb = B + (size_t)nh * KL * QL;
#pragma unroll
    for (int i = 0; i < 4; i++) {
        int f = tid + i * 256;
        int k = f >> 4, qq = (f & 15) * 4;
        float4 v = *(const float4*)(Bb + (size_t)k * QL + qq);
        Bsh[k][qq + 0] = v.x; Bsh[k][qq + 1] = v.y;
        Bsh[k][qq + 2] = v.z; Bsh[k][qq + 3] = v.w;
    }
    __syncthreads();

    const int k = tid & 63;
    const int ebase = tid >> 6;         // 0..3

    float sx[8], sy[8];
#pragma unroll
    for (int i = 0; i < 8; i++) { sx[i] = 0.f; sy[i] = 0.f; }

#pragma unroll 4
    for (int q2 = 0; q2 < 32; q2++) {
        const float2 b = *(const float2*)&Bsh[k][q2 * 2];
#pragma unroll
        for (int i = 0; i < 8; i++) {
            const int e = ebase + i * 4;
            const float2 a = *(const float2*)&Ash[e][q2 * 2];
            sx[i] += fmaxf(a.x + b.x, 0.f);
            sy[i] += fmaxf(a.y + b.y, 0.f);
        }
    }

    float* Tb = T + ((size_t)nh * EE + e0) * KL;
#pragma unroll
    for (int i = 0; i < 8; i++) {
        const int e = ebase + i * 4;
        if (e < ecount)
            Tb[(size_t)e * KL + k] = sx[i] + sy[i];
    }
}

// ---------------------------------------------------------------------------
// Kernel 3b (REWRITE): W[nh][k][q] = sum_e relu(A[e,q]+B[k,q]) * T[e,k]
// grid (64 nh, 2 k-halves of 32), 256 threads.
// Thread: 4 q (float4) x 2 adjacent k. Per e: 1 float4 LDS + 1 float2 LDS + 24 fma.
// B rows in registers; A tile (64e x 64q) + T tile (64e x 32k) in smem.
// ---------------------------------------------------------------------------
__global__ __launch_bounds__(256) void wk_kernel(
    const float* __restrict__ A, const float* __restrict__ B,
    const float* __restrict__ T, float* __restrict__ W)
{
    const int nh = blockIdx.x;
    const int kg = blockIdx.y;          // 0,1

    __shared__ float Ash[64][64];       // [e][q] (256B rows, float4-safe)
    __shared__ float Tsh[64][32];       // [e][k-local] (128B rows, float2-safe)

    const int tid = threadIdx.x;
    const int qx = tid & 15;            // q4 = qx*4
    const int ky = tid >> 4;            // 0..15, k pair
    const int k0 = kg * 32 + ky * 2;
    const int k1 = k0 + 1;

    const float* Bb = B + (size_t)nh * KL * QL;
    const float4 b0 = *(const float4*)(Bb + (size_t)k0 * QL + qx * 4);
    const float4 b1 = *(const float4*)(Bb + (size_t)k1 * QL + qx * 4);

    float4 w0 = make_float4(0.f, 0.f, 0.f, 0.f);
    float4 w1 = make_float4(0.f, 0.f, 0.f, 0.f);

    const float* Ab = A + (size_t)nh * EE * QL;
    const float* Tb = T + (size_t)nh * EE * KL + kg * 32;

    for (int et = 0; et < 5; et++) {
        const int e0 = et * 64;
        const int ec = min(64, EE - e0);        // 64,64,64,64,44
        // load A tile: 4096 floats = 4 float4/thread
#pragma unroll
        for (int i = 0; i < 4; i++) {
            int f = tid + i * 256;
            int e = f >> 4, qq = (f & 15) * 4;
            float4 v = make_float4(0.f, 0.f, 0.f, 0.f);
            if (e < ec) v = *(const float4*)(Ab + (size_t)(e0 + e) * QL + qq);
            *(float4*)&Ash[e][qq] = v;
        }
        // load T tile: 2048 floats = 2 float4/thread
#pragma unroll
        for (int i = 0; i < 2; i++) {
            int f = tid + i * 256;
            int e = f >> 3, kl = (f & 7) * 4;
            float4 v = make_float4(0.f, 0.f, 0.f, 0.f);
            if (e < ec) v = *(const float4*)(Tb + (size_t)(e0 + e) * KL + kl);
            *(float4*)&Tsh[e][kl] = v;
        }
        __syncthreads();

#pragma unroll 8
        for (int e = 0; e < 64; e++) {
            const float4 a = *(const float4*)&Ash[e][qx * 4];
            const float2 t = *(const float2*)&Tsh[e][ky * 2];
            float s;
            s = fmaxf(a.x + b0.x, 0.f); w0.x = fmaf(t.x, s, w0.x);
            s = fmaxf(a.y + b0.y, 0.f); w0.y = fmaf(t.x, s, w0.y);
            s = fmaxf(a.z + b0.z, 0.f); w0.z = fmaf(t.x, s, w0.z);
            s = fmaxf(a.w + b0.w, 0.f); w0.w = fmaf(t.x, s, w0.w);
            s = fmaxf(a.x + b1.x, 0.f); w1.x = fmaf(t.y, s, w1.x);
            s = fmaxf(a.y + b1.y, 0.f); w1.y = fmaf(t.y, s, w1.y);
            s = fmaxf(a.z + b1.z, 0.f); w1.z = fmaf(t.y, s, w1.z);
            s = fmaxf(a.w + b1.w, 0.f); w1.w = fmaf(t.y, s, w1.w);
        }
        __syncthreads();
    }

    float* Wb = W + (size_t)nh * KL * QL;
    *(float4*)(Wb + (size_t)k0 * QL + qx * 4) = w0;
    *(float4*)(Wb + (size_t)k1 * QL + qx * 4) = w1;
}

// ---------------------------------------------------------------------------
// Kernel 4: out[n,q,h,d] = sum_k W[nh][k][q] * V[k,h,d]
// ---------------------------------------------------------------------------
__global__ __launch_bounds__(256) void out_kernel(
    const float* __restrict__ W, const float* __restrict__ V, float* __restrict__ out)
{
    const int nh = blockIdx.x;
    const int n = nh >> 4, h = nh & 15;

    __shared__ float Ws[64][64];   // [k][q]
    __shared__ float Vs[64][48];   // [k][d]

    const int tid = threadIdx.x;
    const float* Wb = W + (size_t)nh * KL * QL;
    for (int i = tid; i < 64 * 64; i += 256)
        Ws[i >> 6][i & 63] = Wb[i];
    for (int i = tid; i < 64 * 48; i += 256) {
        int kk = i / 48, d = i % 48;
        Vs[kk][d] = V[(size_t)kk * DD + h * HD + d];
    }
    __syncthreads();

    const int tx = tid & 15;      // d group of 3
    const int ty = tid >> 4;      // q group of 4
    float acc[4][3];
#pragma unroll
    for (int i = 0; i < 4; i++)
#pragma unroll
        for (int j = 0; j < 3; j++) acc[i][j] = 0.f;

#pragma unroll 4
    for (int kk = 0; kk < 64; kk++) {
        float wq[4], vd[3];
#pragma unroll
        for (int i = 0; i < 4; i++) wq[i] = Ws[kk][ty * 4 + i];
#pragma unroll
        for (int j = 0; j < 3; j++) vd[j] = Vs[kk][tx * 3 + j];
#pragma unroll
        for (int i = 0; i < 4; i++)
#pragma unroll
            for (int j = 0; j < 3; j++)
                acc[i][j] = fmaf(wq[i], vd[j], acc[i][j]);
    }

#pragma unroll
    for (int i = 0; i < 4; i++) {
        int q = ty * 4 + i;
#pragma unroll
        for (int j = 0; j < 3; j++) {
            int d = tx * 3 + j;
            out[(size_t)(n * QL + q) * DD + h * HD + d] = acc[i][j];
        }
    }
}

// ---------------------------------------------------------------------------
// Launch
// Inputs: 0=q 1=k 2=v 3=Wq 4=bq 5=Wk 6=bk 7=Wv 8=bv 9=memory
// ---------------------------------------------------------------------------
extern "C" void kernel_launch(void* const* d_in, const int* in_sizes, int n_in,
                              void* d_out, int out_size)
{
    const float* q   = (const float*)d_in[0];
    const float* k   = (const float*)d_in[1];
    const float* v   = (const float*)d_in[2];
    const float* Wq  = (const float*)d_in[3];
    const float* bq  = (const float*)d_in[4];
    const float* Wk  = (const float*)d_in[5];
    const float* bk  = (const float*)d_in[6];
    const float* Wv  = (const float*)d_in[7];
    const float* bv  = (const float*)d_in[8];
    const float* mem = (const float*)d_in[9];
    float* out = (float*)d_out;

    float *gQ, *gK, *gV, *gA, *gB, *gT, *gW;
    cudaGetSymbolAddress((void**)&gQ, g_Q);
    cudaGetSymbolAddress((void**)&gK, g_K);
    cudaGetSymbolAddress((void**)&gV, g_V);
    cudaGetSymbolAddress((void**)&gA, g_A);
    cudaGetSymbolAddress((void**)&gB, g_B);
    cudaGetSymbolAddress((void**)&gT, g_T);
    cudaGetSymbolAddress((void**)&gW, g_W);

    // 1. Fused projections (one wave)
    proj_kernel<<<dim3(6, 24), 256>>>(q, k, v, Wq, Wk, Wv, bq, bk, bv, gQ, gK, gV);

    // 2. A (mem·Q) and B (K·Q) scores
    scores_kernel<<<dim3(NH, 6), 256>>>(mem, gQ, gK, gA, gB);

    // 3a. T[e,k] row sums (shuffle-free)
    tsum_kernel<<<dim3(NH, 10), 256>>>(gA, gB, gT);

    // 3b. W[k,q] (register-blocked 4q x 2k)
    wk_kernel<<<dim3(NH, 2), 256>>>(gA, gB, gT, gW);

    // 4. out = W^T @ V_h
    out_kernel<<<NH, 256>>>(gW, gV, out);
}

// round 5
// speedup vs baseline: 2.1353x; 1.0510x over previous
#include <cuda_runtime.h>
#include <cuda_bf16.h>

// Problem constants
#define NN 4
#define QL 64
#define KL 64
#define DD 768
#define HH 16
#define HD 48
#define EE 300
#define NH (NN*HH)   // 64

// Scratch (device globals — no allocation allowed). 128B-aligned for float4 access.
__device__ __align__(128) float g_Q[NN*QL*DD];     // [256][768]
__device__ __align__(128) float g_K[KL*DD];        // [64][768]
__device__ __align__(128) float g_V[KL*DD];        // [64][768]
__device__ __align__(128) float g_A[NH*EE*QL];     // [nh][e][q]
__device__ __align__(128) float g_B[NH*KL*QL];     // [nh][k][q]
__device__ __align__(128) float g_T[NH*EE*KL];     // [nh][e][k]
__device__ __align__(128) float g_Wp[3*NH*KL*QL];  // 3 e-partials of [nh][k][q]

// ---------------------------------------------------------------------------
// Kernel 1: fused Q/K/V projections. Y = X @ Wt + bias
// grid (6 row-tiles, 24 col-tiles): rt 0-3 = Q tiles, 4 = K, 5 = V
// ---------------------------------------------------------------------------
__global__ __launch_bounds__(256) void proj_kernel(
    const float* __restrict__ qin, const float* __restrict__ kin,
    const float* __restrict__ vin,
    const float* __restrict__ Wq, const float* __restrict__ Wk,
    const float* __restrict__ Wv,
    const float* __restrict__ bq, const float* __restrict__ bk,
    const float* __restrict__ bv,
    float* __restrict__ Qo, float* __restrict__ Ko, float* __restrict__ Vo)
{
    __shared__ float As[32][64];   // [k][m] transposed (256B rows, float4-safe)
    __shared__ float Bs[32][34];   // [k][c] (136B rows, float2-safe)

    const int rt = blockIdx.x;
    const int c0 = blockIdx.y * 32;
    const float *X, *Wt, *bias;
    float* Y;
    if (rt < 4)      { X = qin + (size_t)rt * 64 * DD; Wt = Wq; bias = bq; Y = Qo + (size_t)rt * 64 * DD; }
    else if (rt == 4){ X = kin; Wt = Wk; bias = bk; Y = Ko; }
    else             { X = vin; Wt = Wv; bias = bv; Y = Vo; }

    const int tid = threadIdx.x;
    const int tx = tid & 15;       // col group (2 cols)
    const int ty = tid >> 4;       // row group (4 rows)
    const int lr = tid >> 2;       // A load row 0..63
    const int lc = (tid & 3) * 4;  // A load k-offset (and +16)
    const int br = tid >> 3;       // B load k-row 0..31
    const int bc = (tid & 7) * 4;  // B load col

    float acc[4][2];
#pragma unroll
    for (int i = 0; i < 4; i++) { acc[i][0] = 0.f; acc[i][1] = 0.f; }

    for (int k0 = 0; k0 < DD; k0 += 32) {
        const float4 a0 = *(const float4*)(X + (size_t)lr * DD + k0 + lc);
        const float4 a1 = *(const float4*)(X + (size_t)lr * DD + k0 + lc + 16);
        const float4 bb = *(const float4*)(Wt + (size_t)(k0 + br) * DD + c0 + bc);
        As[lc + 0][lr] = a0.x; As[lc + 1][lr] = a0.y;
        As[lc + 2][lr] = a0.z; As[lc + 3][lr] = a0.w;
        As[lc + 16][lr] = a1.x; As[lc + 17][lr] = a1.y;
        As[lc + 18][lr] = a1.z; As[lc + 19][lr] = a1.w;
        Bs[br][bc + 0] = bb.x; Bs[br][bc + 1] = bb.y;
        Bs[br][bc + 2] = bb.z; Bs[br][bc + 3] = bb.w;
        __syncthreads();
#pragma unroll
        for (int kk = 0; kk < 32; kk++) {
            const float4 a = *(const float4*)&As[kk][ty * 4];
            const float2 b = *(const float2*)&Bs[kk][tx * 2];
            acc[0][0] = fmaf(a.x, b.x, acc[0][0]); acc[0][1] = fmaf(a.x, b.y, acc[0][1]);
            acc[1][0] = fmaf(a.y, b.x, acc[1][0]); acc[1][1] = fmaf(a.y, b.y, acc[1][1]);
            acc[2][0] = fmaf(a.z, b.x, acc[2][0]); acc[2][1] = fmaf(a.z, b.y, acc[2][1]);
            acc[3][0] = fmaf(a.w, b.x, acc[3][0]); acc[3][1] = fmaf(a.w, b.y, acc[3][1]);
        }
        __syncthreads();
    }

    const float b0 = bias[c0 + tx * 2];
    const float b1 = bias[c0 + tx * 2 + 1];
#pragma unroll
    for (int i = 0; i < 4; i++) {
        float2 o = make_float2(acc[i][0] + b0, acc[i][1] + b1);
        *(float2*)(Y + (size_t)(ty * 4 + i) * DD + c0 + tx * 2) = o;
    }
}

// ---------------------------------------------------------------------------
// Kernel 2: per (n,h) scores
//   task<5 : A[nh][e][q] = sum_d mem[e,h,d] * Q[n,q,h,d]   (e-tile of 64)
//   task=5 : B[nh][k][q] = sum_d K[k,h,d]  * Q[n,q,h,d]
// ---------------------------------------------------------------------------
__global__ __launch_bounds__(256) void scores_kernel(
    const float* __restrict__ mem, const float* __restrict__ Q,
    const float* __restrict__ K, float* __restrict__ A, float* __restrict__ B)
{
    const int nh = blockIdx.x;          // 0..63
    const int n = nh >> 4, h = nh & 15;
    const int task = blockIdx.y;        // 0..4 = A e-tiles, 5 = B

    __shared__ float Ls[48][68];        // [d][r] (272B rows, float4-safe)
    __shared__ float Qs[48][68];        // [d][q]

    const int tid = threadIdx.x;
    const int r = tid >> 2;             // 0..63
    const int c = tid & 3;

    const float* lbase;
    int R;
    if (task < 5) { lbase = mem + (size_t)task * 64 * DD + h * HD; R = min(64, EE - task * 64); }
    else          { lbase = K + h * HD; R = 64; }

    {
        const float* srcL = lbase + (size_t)r * DD;
        const float* srcQ = Q + (size_t)(n * QL + r) * DD + h * HD;
#pragma unroll
        for (int j = 0; j < 3; j++) {
            const int d0 = c * 4 + j * 16;
            float4 vl = make_float4(0.f, 0.f, 0.f, 0.f);
            if (r < R) vl = *(const float4*)(srcL + d0);
            Ls[d0 + 0][r] = vl.x; Ls[d0 + 1][r] = vl.y;
            Ls[d0 + 2][r] = vl.z; Ls[d0 + 3][r] = vl.w;
            const float4 vq = *(const float4*)(srcQ + d0);
            Qs[d0 + 0][r] = vq.x; Qs[d0 + 1][r] = vq.y;
            Qs[d0 + 2][r] = vq.z; Qs[d0 + 3][r] = vq.w;
        }
    }
    __syncthreads();

    const int tx = tid & 15, ty = tid >> 4;
    float acc[4][4];
#pragma unroll
    for (int i = 0; i < 4; i++)
#pragma unroll
        for (int j = 0; j < 4; j++) acc[i][j] = 0.f;

#pragma unroll 8
    for (int d = 0; d < 48; d++) {
        const float4 a = *(const float4*)&Ls[d][ty * 4];
        const float4 b = *(const float4*)&Qs[d][tx * 4];
        acc[0][0] = fmaf(a.x, b.x, acc[0][0]); acc[0][1] = fmaf(a.x, b.y, acc[0][1]);
        acc[0][2] = fmaf(a.x, b.z, acc[0][2]); acc[0][3] = fmaf(a.x, b.w, acc[0][3]);
        acc[1][0] = fmaf(a.y, b.x, acc[1][0]); acc[1][1] = fmaf(a.y, b.y, acc[1][1]);
        acc[1][2] = fmaf(a.y, b.z, acc[1][2]); acc[1][3] = fmaf(a.y, b.w, acc[1][3]);
        acc[2][0] = fmaf(a.z, b.x, acc[2][0]); acc[2][1] = fmaf(a.z, b.y, acc[2][1]);
        acc[2][2] = fmaf(a.z, b.z, acc[2][2]); acc[2][3] = fmaf(a.z, b.w, acc[2][3]);
        acc[3][0] = fmaf(a.w, b.x, acc[3][0]); acc[3][1] = fmaf(a.w, b.y, acc[3][1]);
        acc[3][2] = fmaf(a.w, b.z, acc[3][2]); acc[3][3] = fmaf(a.w, b.w, acc[3][3]);
    }

    if (task < 5) {
        float* out = A + (size_t)nh * EE * QL;
#pragma unroll
        for (int i = 0; i < 4; i++) {
            int e = task * 64 + ty * 4 + i;
            if (e < EE) {
                float4 o = make_float4(acc[i][0], acc[i][1], acc[i][2], acc[i][3]);
                *(float4*)(out + (size_t)e * QL + tx * 4) = o;
            }
        }
    } else {
        float* out = B + (size_t)nh * KL * QL;
#pragma unroll
        for (int i = 0; i < 4; i++) {
            float4 o = make_float4(acc[i][0], acc[i][1], acc[i][2], acc[i][3]);
            *(float4*)(out + (size_t)(ty * 4 + i) * QL + tx * 4) = o;
        }
    }
}

// ---------------------------------------------------------------------------
// Kernel 3a: T[nh][e][k] = sum_q relu(A[nh][e][q] + B[nh][k][q])
// grid (64, 10 e-tiles of 32), 256 threads.
// ---------------------------------------------------------------------------
__global__ __launch_bounds__(256) void tsum_kernel(
    const float* __restrict__ A, const float* __restrict__ B, float* __restrict__ T)
{
    const int nh = blockIdx.x;
    const int e0 = blockIdx.y * 32;
    const int ecount = min(32, EE - e0);

    __shared__ float Ash[32][64];       // [e][q] (256B rows)
    __shared__ float Bsh[64][66];       // [k][q] (264B rows, float2-safe)

    const int tid = threadIdx.x;
    const float* Ab = A + ((size_t)nh * EE + e0) * QL;
#pragma unroll
    for (int i = 0; i < 2; i++) {
        int f = tid + i * 256;          // float4 index
        int e = f >> 4, qq = (f & 15) * 4;
        float4 v = make_float4(0.f, 0.f, 0.f, 0.f);
        if (e < ecount) v = *(const float4*)(Ab + (size_t)e * QL + qq);
        *(float4*)&Ash[e][qq] = v;
    }
    const float* Bb = B + (size_t)nh * KL * QL;
#pragma unroll
    for (int i = 0; i < 4; i++) {
        int f = tid + i * 256;
        int k = f >> 4, qq = (f & 15) * 4;
        float4 v = *(const float4*)(Bb + (size_t)k * QL + qq);
        Bsh[k][qq + 0] = v.x; Bsh[k][qq + 1] = v.y;
        Bsh[k][qq + 2] = v.z; Bsh[k][qq + 3] = v.w;
    }
    __syncthreads();

    const int k = tid & 63;
    const int ebase = tid >> 6;         // 0..3

    float sx[8], sy[8];
#pragma unroll
    for (int i = 0; i < 8; i++) { sx[i] = 0.f; sy[i] = 0.f; }

#pragma unroll 4
    for (int q2 = 0; q2 < 32; q2++) {
        const float2 b = *(const float2*)&Bsh[k][q2 * 2];
#pragma unroll
        for (int i = 0; i < 8; i++) {
            const int e = ebase + i * 4;
            const float2 a = *(const float2*)&Ash[e][q2 * 2];
            sx[i] += fmaxf(a.x + b.x, 0.f);
            sy[i] += fmaxf(a.y + b.y, 0.f);
        }
    }

    float* Tb = T + ((size_t)nh * EE + e0) * KL;
#pragma unroll
    for (int i = 0; i < 8; i++) {
        const int e = ebase + i * 4;
        if (e < ecount)
            Tb[(size_t)e * KL + k] = sx[i] + sy[i];
    }
}

// ---------------------------------------------------------------------------
// Kernel 3b: Wp[es][nh][k][q] = sum_{e in third} relu(A[e,q]+B[k,q]) * T[e,k]
// grid (64 nh, 2 k-halves, 3 e-thirds of 100), 256 threads. Deterministic
// partials (no atomics); out_kernel sums the 3 buffers.
// Thread: 4 q (float4) x 2 adjacent k.
// ---------------------------------------------------------------------------
__global__ __launch_bounds__(256) void wk_kernel(
    const float* __restrict__ A, const float* __restrict__ B,
    const float* __restrict__ T, float* __restrict__ Wp)
{
    const int nh = blockIdx.x;
    const int kg = blockIdx.y;          // 0,1
    const int es = blockIdx.z;          // 0,1,2
    const int estart = es * 100;
    const int eend = min(EE, estart + 100);

    __shared__ float Ash[64][64];       // [e][q] (256B rows, float4-safe)
    __shared__ float Tsh[64][32];       // [e][k-local] (128B rows, float2-safe)

    const int tid = threadIdx.x;
    const int qx = tid & 15;            // q4 = qx*4
    const int ky = tid >> 4;            // 0..15, k pair
    const int k0 = kg * 32 + ky * 2;
    const int k1 = k0 + 1;

    const float* Bb = B + (size_t)nh * KL * QL;
    const float4 b0 = *(const float4*)(Bb + (size_t)k0 * QL + qx * 4);
    const float4 b1 = *(const float4*)(Bb + (size_t)k1 * QL + qx * 4);

    float4 w0 = make_float4(0.f, 0.f, 0.f, 0.f);
    float4 w1 = make_float4(0.f, 0.f, 0.f, 0.f);

    const float* Ab = A + (size_t)nh * EE * QL;
    const float* Tb = T + (size_t)nh * EE * KL + kg * 32;

    for (int e0 = estart; e0 < eend; e0 += 64) {
        const int ec = min(64, eend - e0);      // 64, 36
        // load A tile: 4 float4/thread (zero-pad beyond ec; padded T=0 kills it)
#pragma unroll
        for (int i = 0; i < 4; i++) {
            int f = tid + i * 256;
            int e = f >> 4, qq = (f & 15) * 4;
            float4 v = make_float4(0.f, 0.f, 0.f, 0.f);
            if (e < ec) v = *(const float4*)(Ab + (size_t)(e0 + e) * QL + qq);
            *(float4*)&Ash[e][qq] = v;
        }
        // load T tile: 2 float4/thread
#pragma unroll
        for (int i = 0; i < 2; i++) {
            int f = tid + i * 256;
            int e = f >> 3, kl = (f & 7) * 4;
            float4 v = make_float4(0.f, 0.f, 0.f, 0.f);
            if (e < ec) v = *(const float4*)(Tb + (size_t)(e0 + e) * KL + kl);
            *(float4*)&Tsh[e][kl] = v;
        }
        __syncthreads();

#pragma unroll 8
        for (int e = 0; e < 64; e++) {
            const float4 a = *(const float4*)&Ash[e][qx * 4];
            const float2 t = *(const float2*)&Tsh[e][ky * 2];
            float s;
            s = fmaxf(a.x + b0.x, 0.f); w0.x = fmaf(t.x, s, w0.x);
            s = fmaxf(a.y + b0.y, 0.f); w0.y = fmaf(t.x, s, w0.y);
            s = fmaxf(a.z + b0.z, 0.f); w0.z = fmaf(t.x, s, w0.z);
            s = fmaxf(a.w + b0.w, 0.f); w0.w = fmaf(t.x, s, w0.w);
            s = fmaxf(a.x + b1.x, 0.f); w1.x = fmaf(t.y, s, w1.x);
            s = fmaxf(a.y + b1.y, 0.f); w1.y = fmaf(t.y, s, w1.y);
            s = fmaxf(a.z + b1.z, 0.f); w1.z = fmaf(t.y, s, w1.z);
            s = fmaxf(a.w + b1.w, 0.f); w1.w = fmaf(t.y, s, w1.w);
        }
        __syncthreads();
    }

    float* Wb = Wp + ((size_t)es * NH + nh) * KL * QL;
    *(float4*)(Wb + (size_t)k0 * QL + qx * 4) = w0;
    *(float4*)(Wb + (size_t)k1 * QL + qx * 4) = w1;
}

// ---------------------------------------------------------------------------
// Kernel 4: out[n,q,h,d] = sum_k (Wp0+Wp1+Wp2)[nh][k][q] * V[k,h,d]
// ---------------------------------------------------------------------------
__global__ __launch_bounds__(256) void out_kernel(
    const float* __restrict__ Wp, const float* __restrict__ V, float* __restrict__ out)
{
    const int nh = blockIdx.x;
    const int n = nh >> 4, h = nh & 15;

    __shared__ float Ws[64][64];   // [k][q]
    __shared__ float Vs[64][48];   // [k][d]

    const int tid = threadIdx.x;
    const float* W0 = Wp + (size_t)nh * KL * QL;
    const float* W1 = W0 + (size_t)NH * KL * QL;
    const float* W2 = W1 + (size_t)NH * KL * QL;
    for (int i = tid; i < 64 * 64 / 4; i += 256) {
        const float4 a = *(const float4*)(W0 + i * 4);
        const float4 b = *(const float4*)(W1 + i * 4);
        const float4 c = *(const float4*)(W2 + i * 4);
        float4 s = make_float4(a.x + b.x + c.x, a.y + b.y + c.y,
                               a.z + b.z + c.z, a.w + b.w + c.w);
        *(float4*)&Ws[(i * 4) >> 6][(i * 4) & 63] = s;
    }
    for (int i = tid; i < 64 * 48; i += 256) {
        int kk = i / 48, d = i % 48;
        Vs[kk][d] = V[(size_t)kk * DD + h * HD + d];
    }
    __syncthreads();

    const int tx = tid & 15;      // d group of 3
    const int ty = tid >> 4;      // q group of 4
    float acc[4][3];
#pragma unroll
    for (int i = 0; i < 4; i++)
#pragma unroll
        for (int j = 0; j < 3; j++) acc[i][j] = 0.f;

#pragma unroll 4
    for (int kk = 0; kk < 64; kk++) {
        float wq[4], vd[3];
#pragma unroll
        for (int i = 0; i < 4; i++) wq[i] = Ws[kk][ty * 4 + i];
#pragma unroll
        for (int j = 0; j < 3; j++) vd[j] = Vs[kk][tx * 3 + j];
#pragma unroll
        for (int i = 0; i < 4; i++)
#pragma unroll
            for (int j = 0; j < 3; j++)
                acc[i][j] = fmaf(wq[i], vd[j], acc[i][j]);
    }

#pragma unroll
    for (int i = 0; i < 4; i++) {
        int q = ty * 4 + i;
#pragma unroll
        for (int j = 0; j < 3; j++) {
            int d = tx * 3 + j;
            out[(size_t)(n * QL + q) * DD + h * HD + d] = acc[i][j];
        }
    }
}

// ---------------------------------------------------------------------------
// Launch
// Inputs: 0=q 1=k 2=v 3=Wq 4=bq 5=Wk 6=bk 7=Wv 8=bv 9=memory
// ---------------------------------------------------------------------------
extern "C" void kernel_launch(void* const* d_in, const int* in_sizes, int n_in,
                              void* d_out, int out_size)
{
    const float* q   = (const float*)d_in[0];
    const float* k   = (const float*)d_in[1];
    const float* v   = (const float*)d_in[2];
    const float* Wq  = (const float*)d_in[3];
    const float* bq  = (const float*)d_in[4];
    const float* Wk  = (const float*)d_in[5];
    const float* bk  = (const float*)d_in[6];
    const float* Wv  = (const float*)d_in[7];
    const float* bv  = (const float*)d_in[8];
    const float* mem = (const float*)d_in[9];
    float* out = (float*)d_out;

    float *gQ, *gK, *gV, *gA, *gB, *gT, *gWp;
    cudaGetSymbolAddress((void**)&gQ, g_Q);
    cudaGetSymbolAddress((void**)&gK, g_K);
    cudaGetSymbolAddress((void**)&gV, g_V);
    cudaGetSymbolAddress((void**)&gA, g_A);
    cudaGetSymbolAddress((void**)&gB, g_B);
    cudaGetSymbolAddress((void**)&gT, g_T);
    cudaGetSymbolAddress((void**)&gWp, g_Wp);

    // 1. Fused projections (one wave)
    proj_kernel<<<dim3(6, 24), 256>>>(q, k, v, Wq, Wk, Wv, bq, bk, bv, gQ, gK, gV);

    // 2. A (mem·Q) and B (K·Q) scores
    scores_kernel<<<dim3(NH, 6), 256>>>(mem, gQ, gK, gA, gB);

    // 3a. T[e,k] row sums (shuffle-free)
    tsum_kernel<<<dim3(NH, 10), 256>>>(gA, gB, gT);

    // 3b. W partials over 3 e-thirds (384 blocks for occupancy)
    wk_kernel<<<dim3(NH, 2, 3), 256>>>(gA, gB, gT, gWp);

    // 4. out = (sum of W partials)^T @ V_h
    out_kernel<<<NH, 256>>>(gWp, gV, out);
}

// round 7
// speedup vs baseline: 2.2627x; 1.0597x over previous
#include <cuda_runtime.h>
#include <cuda_bf16.h>

// Problem constants
#define NN 4
#define QL 64
#define KL 64
#define DD 768
#define HH 16
#define HD 48
#define EE 300
#define NH (NN*HH)   // 64

// Scratch (device globals — no allocation allowed). 128B-aligned for float4 access.
__device__ __align__(128) float g_Q[NN*QL*DD];     // [256][768]
__device__ __align__(128) float g_K[KL*DD];        // [64][768]
__device__ __align__(128) float g_V[KL*DD];        // [64][768]
__device__ __align__(128) float g_A[NH*EE*QL];     // [nh][e][q]
__device__ __align__(128) float g_B[NH*KL*QL];     // [nh][k][q]
__device__ __align__(128) float g_Wp[3*NH*KL*QL];  // 3 e-partials of [nh][k][q]

// ---------------------------------------------------------------------------
// Kernel 1: fused Q/K/V projections. Y = X @ Wt + bias
// grid (6 row-tiles, 24 col-tiles): rt 0-3 = Q tiles, 4 = K, 5 = V
// ---------------------------------------------------------------------------
__global__ __launch_bounds__(256) void proj_kernel(
    const float* __restrict__ qin, const float* __restrict__ kin,
    const float* __restrict__ vin,
    const float* __restrict__ Wq, const float* __restrict__ Wk,
    const float* __restrict__ Wv,
    const float* __restrict__ bq, const float* __restrict__ bk,
    const float* __restrict__ bv,
    float* __restrict__ Qo, float* __restrict__ Ko, float* __restrict__ Vo)
{
    __shared__ float As[32][64];   // [k][m] transposed (256B rows, float4-safe)
    __shared__ float Bs[32][34];   // [k][c] (136B rows, float2-safe)

    const int rt = blockIdx.x;
    const int c0 = blockIdx.y * 32;
    const float *X, *Wt, *bias;
    float* Y;
    if (rt < 4)      { X = qin + (size_t)rt * 64 * DD; Wt = Wq; bias = bq; Y = Qo + (size_t)rt * 64 * DD; }
    else if (rt == 4){ X = kin; Wt = Wk; bias = bk; Y = Ko; }
    else             { X = vin; Wt = Wv; bias = bv; Y = Vo; }

    const int tid = threadIdx.x;
    const int tx = tid & 15;       // col group (2 cols)
    const int ty = tid >> 4;       // row group (4 rows)
    const int lr = tid >> 2;       // A load row 0..63
    const int lc = (tid & 3) * 4;  // A load k-offset (and +16)
    const int br = tid >> 3;       // B load k-row 0..31
    const int bc = (tid & 7) * 4;  // B load col

    float acc[4][2];
#pragma unroll
    for (int i = 0; i < 4; i++) { acc[i][0] = 0.f; acc[i][1] = 0.f; }

    for (int k0 = 0; k0 < DD; k0 += 32) {
        const float4 a0 = *(const float4*)(X + (size_t)lr * DD + k0 + lc);
        const float4 a1 = *(const float4*)(X + (size_t)lr * DD + k0 + lc + 16);
        const float4 bb = *(const float4*)(Wt + (size_t)(k0 + br) * DD + c0 + bc);
        As[lc + 0][lr] = a0.x; As[lc + 1][lr] = a0.y;
        As[lc + 2][lr] = a0.z; As[lc + 3][lr] = a0.w;
        As[lc + 16][lr] = a1.x; As[lc + 17][lr] = a1.y;
        As[lc + 18][lr] = a1.z; As[lc + 19][lr] = a1.w;
        Bs[br][bc + 0] = bb.x; Bs[br][bc + 1] = bb.y;
        Bs[br][bc + 2] = bb.z; Bs[br][bc + 3] = bb.w;
        __syncthreads();
#pragma unroll
        for (int kk = 0; kk < 32; kk++) {
            const float4 a = *(const float4*)&As[kk][ty * 4];
            const float2 b = *(const float2*)&Bs[kk][tx * 2];
            acc[0][0] = fmaf(a.x, b.x, acc[0][0]); acc[0][1] = fmaf(a.x, b.y, acc[0][1]);
            acc[1][0] = fmaf(a.y, b.x, acc[1][0]); acc[1][1] = fmaf(a.y, b.y, acc[1][1]);
            acc[2][0] = fmaf(a.z, b.x, acc[2][0]); acc[2][1] = fmaf(a.z, b.y, acc[2][1]);
            acc[3][0] = fmaf(a.w, b.x, acc[3][0]); acc[3][1] = fmaf(a.w, b.y, acc[3][1]);
        }
        __syncthreads();
    }

    const float b0 = bias[c0 + tx * 2];
    const float b1 = bias[c0 + tx * 2 + 1];
#pragma unroll
    for (int i = 0; i < 4; i++) {
        float2 o = make_float2(acc[i][0] + b0, acc[i][1] + b1);
        *(float2*)(Y + (size_t)(ty * 4 + i) * DD + c0 + tx * 2) = o;
    }
}

// ---------------------------------------------------------------------------
// Kernel 2: per (n,h) scores
//   task<5 : A[nh][e][q] = sum_d mem[e,h,d] * Q[n,q,h,d]   (e-tile of 64)
//   task=5 : B[nh][k][q] = sum_d K[k,h,d]  * Q[n,q,h,d]
// ---------------------------------------------------------------------------
__global__ __launch_bounds__(256) void scores_kernel(
    const float* __restrict__ mem, const float* __restrict__ Q,
    const float* __restrict__ K, float* __restrict__ A, float* __restrict__ B)
{
    const int nh = blockIdx.x;          // 0..63
    const int n = nh >> 4, h = nh & 15;
    const int task = blockIdx.y;        // 0..4 = A e-tiles, 5 = B

    __shared__ float Ls[48][68];        // [d][r] (272B rows, float4-safe)
    __shared__ float Qs[48][68];        // [d][q]

    const int tid = threadIdx.x;
    const int r = tid >> 2;             // 0..63
    const int c = tid & 3;

    const float* lbase;
    int R;
    if (task < 5) { lbase = mem + (size_t)task * 64 * DD + h * HD; R = min(64, EE - task * 64); }
    else          { lbase = K + h * HD; R = 64; }

    {
        const float* srcL = lbase + (size_t)r * DD;
        const float* srcQ = Q + (size_t)(n * QL + r) * DD + h * HD;
#pragma unroll
        for (int j = 0; j < 3; j++) {
            const int d0 = c * 4 + j * 16;
            float4 vl = make_float4(0.f, 0.f, 0.f, 0.f);
            if (r < R) vl = *(const float4*)(srcL + d0);
            Ls[d0 + 0][r] = vl.x; Ls[d0 + 1][r] = vl.y;
            Ls[d0 + 2][r] = vl.z; Ls[d0 + 3][r] = vl.w;
            const float4 vq = *(const float4*)(srcQ + d0);
            Qs[d0 + 0][r] = vq.x; Qs[d0 + 1][r] = vq.y;
            Qs[d0 + 2][r] = vq.z; Qs[d0 + 3][r] = vq.w;
        }
    }
    __syncthreads();

    const int tx = tid & 15, ty = tid >> 4;
    float acc[4][4];
#pragma unroll
    for (int i = 0; i < 4; i++)
#pragma unroll
        for (int j = 0; j < 4; j++) acc[i][j] = 0.f;

#pragma unroll 8
    for (int d = 0; d < 48; d++) {
        const float4 a = *(const float4*)&Ls[d][ty * 4];
        const float4 b = *(const float4*)&Qs[d][tx * 4];
        acc[0][0] = fmaf(a.x, b.x, acc[0][0]); acc[0][1] = fmaf(a.x, b.y, acc[0][1]);
        acc[0][2] = fmaf(a.x, b.z, acc[0][2]); acc[0][3] = fmaf(a.x, b.w, acc[0][3]);
        acc[1][0] = fmaf(a.y, b.x, acc[1][0]); acc[1][1] = fmaf(a.y, b.y, acc[1][1]);
        acc[1][2] = fmaf(a.y, b.z, acc[1][2]); acc[1][3] = fmaf(a.y, b.w, acc[1][3]);
        acc[2][0] = fmaf(a.z, b.x, acc[2][0]); acc[2][1] = fmaf(a.z, b.y, acc[2][1]);
        acc[2][2] = fmaf(a.z, b.z, acc[2][2]); acc[2][3] = fmaf(a.z, b.w, acc[2][3]);
        acc[3][0] = fmaf(a.w, b.x, acc[3][0]); acc[3][1] = fmaf(a.w, b.y, acc[3][1]);
        acc[3][2] = fmaf(a.w, b.z, acc[3][2]); acc[3][3] = fmaf(a.w, b.w, acc[3][3]);
    }

    if (task < 5) {
        float* out = A + (size_t)nh * EE * QL;
#pragma unroll
        for (int i = 0; i < 4; i++) {
            int e = task * 64 + ty * 4 + i;
            if (e < EE) {
                float4 o = make_float4(acc[i][0], acc[i][1], acc[i][2], acc[i][3]);
                *(float4*)(out + (size_t)e * QL + tx * 4) = o;
            }
        }
    } else {
        float* out = B + (size_t)nh * KL * QL;
#pragma unroll
        for (int i = 0; i < 4; i++) {
            float4 o = make_float4(acc[i][0], acc[i][1], acc[i][2], acc[i][3]);
            *(float4*)(out + (size_t)(ty * 4 + i) * QL + tx * 4) = o;
        }
    }
}

// ---------------------------------------------------------------------------
// Kernel 3 (FUSED tsum+wk):
//   per 64-e tile: pass1 Tsh[e][k] = sum_q relu(A[e,q]+B[k,q]) (k local 0..31)
//                  pass2 w[k,q] += relu(A[e,q]+B[k,q]) * Tsh[e][k]
// grid (64 nh, 2 k-halves of 32, 3 e-thirds of 100), 256 threads.
// Deterministic partials -> g_Wp; out_kernel sums the 3 buffers.
// ---------------------------------------------------------------------------
__global__ __launch_bounds__(256) void wkfused_kernel(
    const float* __restrict__ A, const float* __restrict__ B,
    float* __restrict__ Wp)
{
    const int nh = blockIdx.x;
    const int kg = blockIdx.y;          // 0,1
    const int es = blockIdx.z;          // 0,1,2
    const int estart = es * 100;
    const int eend = min(EE, estart + 100);

    __shared__ float Ash[64][64];       // [e][q] (256B rows, float4-safe)
    __shared__ float Bsh[32][66];       // [k-local][q] (264B rows, float2-safe)
    __shared__ float Tsh[64][32];       // [e][k-local]

    const int tid = threadIdx.x;
    const int qx = tid & 15;            // pass2: q4 = qx*4
    const int ky = tid >> 4;            // pass2: local k pair = ky*2, ky*2+1
    const int kp = tid & 31;            // pass1: local k
    const int eb = tid >> 5;            // pass1: warp -> e group of 8

    const float* Bb = B + ((size_t)nh * KL + kg * 32) * QL;

    // load Bsh once (32 x 64)
#pragma unroll
    for (int i = 0; i < 2; i++) {
        int f = tid + i * 256;
        int k = f >> 4, qq = (f & 15) * 4;
        float4 v = *(const float4*)(Bb + (size_t)k * QL + qq);
        Bsh[k][qq + 0] = v.x; Bsh[k][qq + 1] = v.y;
        Bsh[k][qq + 2] = v.z; Bsh[k][qq + 3] = v.w;
    }

    // pass2 per-thread B registers
    const float4 b0 = *(const float4*)(Bb + (size_t)(ky * 2) * QL + qx * 4);
    const float4 b1 = *(const float4*)(Bb + (size_t)(ky * 2 + 1) * QL + qx * 4);

    float4 w0 = make_float4(0.f, 0.f, 0.f, 0.f);
    float4 w1 = make_float4(0.f, 0.f, 0.f, 0.f);

    const float* Ab = A + (size_t)nh * EE * QL;

    for (int e0 = estart; e0 < eend; e0 += 64) {
        const int ec = min(64, eend - e0);      // 64 or 36
        __syncthreads();    // protect Ash/Tsh from previous pass2 readers
        // load A tile: 4 float4/thread (zero-pad beyond ec)
#pragma unroll
        for (int i = 0; i < 4; i++) {
            int f = tid + i * 256;
            int e = f >> 4, qq = (f & 15) * 4;
            float4 v = make_float4(0.f, 0.f, 0.f, 0.f);
            if (e < ec) v = *(const float4*)(Ab + (size_t)(e0 + e) * QL + qq);
            *(float4*)&Ash[e][qq] = v;
        }
        __syncthreads();

        // pass1: each thread sums 8 e rows (e = eb*8 + i) over all 64 q
        {
            float tacc[8];
#pragma unroll
            for (int i = 0; i < 8; i++) tacc[i] = 0.f;
#pragma unroll 4
            for (int q2 = 0; q2 < 32; q2++) {
                const float2 b = *(const float2*)&Bsh[kp][q2 * 2];
#pragma unroll
                for (int i = 0; i < 8; i++) {
                    const float2 a = *(const float2*)&Ash[eb * 8 + i][q2 * 2];
                    tacc[i] += fmaxf(a.x + b.x, 0.f) + fmaxf(a.y + b.y, 0.f);
                }
            }
#pragma unroll
            for (int i = 0; i < 8; i++) {
                const int e = eb * 8 + i;
                Tsh[e][kp] = (e < ec) ? tacc[i] : 0.f;  // zero padded rows
            }
        }
        __syncthreads();

        // pass2: microtile accumulate
#pragma unroll 8
        for (int e = 0; e < 64; e++) {
            const float4 a = *(const float4*)&Ash[e][qx * 4];
            const float2 t = *(const float2*)&Tsh[e][ky * 2];
            float s;
            s = fmaxf(a.x + b0.x, 0.f); w0.x = fmaf(t.x, s, w0.x);
            s = fmaxf(a.y + b0.y, 0.f); w0.y = fmaf(t.x, s, w0.y);
            s = fmaxf(a.z + b0.z, 0.f); w0.z = fmaf(t.x, s, w0.z);
            s = fmaxf(a.w + b0.w, 0.f); w0.w = fmaf(t.x, s, w0.w);
            s = fmaxf(a.x + b1.x, 0.f); w1.x = fmaf(t.y, s, w1.x);
            s = fmaxf(a.y + b1.y, 0.f); w1.y = fmaf(t.y, s, w1.y);
            s = fmaxf(a.z + b1.z, 0.f); w1.z = fmaf(t.y, s, w1.z);
            s = fmaxf(a.w + b1.w, 0.f); w1.w = fmaf(t.y, s, w1.w);
        }
    }

    float* Wb = Wp + ((size_t)es * NH + nh) * KL * QL + (size_t)kg * 32 * QL;
    *(float4*)(Wb + (size_t)(ky * 2) * QL + qx * 4)     = w0;
    *(float4*)(Wb + (size_t)(ky * 2 + 1) * QL + qx * 4) = w1;
}

// ---------------------------------------------------------------------------
// Kernel 4: out[n,q,h,d] = sum_k (Wp0+Wp1+Wp2)[nh][k][q] * V[k,h,d]
// ---------------------------------------------------------------------------
__global__ __launch_bounds__(256) void out_kernel(
    const float* __restrict__ Wp, const float* __restrict__ V, float* __restrict__ out)
{
    const int nh = blockIdx.x;
    const int n = nh >> 4, h = nh & 15;

    __shared__ float Ws[64][64];   // [k][q]
    __shared__ float Vs[64][48];   // [k][d]

    const int tid = threadIdx.x;
    const float* W0 = Wp + (size_t)nh * KL * QL;
    const float* W1 = W0 + (size_t)NH * KL * QL;
    const float* W2 = W1 + (size_t)NH * KL * QL;
    for (int i = tid; i < 64 * 64 / 4; i += 256) {
        const float4 a = *(const float4*)(W0 + i * 4);
        const float4 b = *(const float4*)(W1 + i * 4);
        const float4 c = *(const float4*)(W2 + i * 4);
        float4 s = make_float4(a.x + b.x + c.x, a.y + b.y + c.y,
                               a.z + b.z + c.z, a.w + b.w + c.w);
        *(float4*)&Ws[(i * 4) >> 6][(i * 4) & 63] = s;
    }
    for (int i = tid; i < 64 * 48; i += 256) {
        int kk = i / 48, d = i % 48;
        Vs[kk][d] = V[(size_t)kk * DD + h * HD + d];
    }
    __syncthreads();

    const int tx = tid & 15;      // d group of 3
    const int ty = tid >> 4;      // q group of 4
    float acc[4][3];
#pragma unroll
    for (int i = 0; i < 4; i++)
#pragma unroll
        for (int j = 0; j < 3; j++) acc[i][j] = 0.f;

#pragma unroll 4
    for (int kk = 0; kk < 64; kk++) {
        float wq[4], vd[3];
#pragma unroll
        for (int i = 0; i < 4; i++) wq[i] = Ws[kk][ty * 4 + i];
#pragma unroll
        for (int j = 0; j < 3; j++) vd[j] = Vs[kk][tx * 3 + j];
#pragma unroll
        for (int i = 0; i < 4; i++)
#pragma unroll
            for (int j = 0; j < 3; j++)
                acc[i][j] = fmaf(wq[i], vd[j], acc[i][j]);
    }

#pragma unroll
    for (int i = 0; i < 4; i++) {
        int q = ty * 4 + i;
#pragma unroll
        for (int j = 0; j < 3; j++) {
            int d = tx * 3 + j;
            out[(size_t)(n * QL + q) * DD + h * HD + d] = acc[i][j];
        }
    }
}

// ---------------------------------------------------------------------------
// Launch
// Inputs: 0=q 1=k 2=v 3=Wq 4=bq 5=Wk 6=bk 7=Wv 8=bv 9=memory
// ---------------------------------------------------------------------------
extern "C" void kernel_launch(void* const* d_in, const int* in_sizes, int n_in,
                              void* d_out, int out_size)
{
    const float* q   = (const float*)d_in[0];
    const float* k   = (const float*)d_in[1];
    const float* v   = (const float*)d_in[2];
    const float* Wq  = (const float*)d_in[3];
    const float* bq  = (const float*)d_in[4];
    const float* Wk  = (const float*)d_in[5];
    const float* bk  = (const float*)d_in[6];
    const float* Wv  = (const float*)d_in[7];
    const float* bv  = (const float*)d_in[8];
    const float* mem = (const float*)d_in[9];
    float* out = (float*)d_out;

    float *gQ, *gK, *gV, *gA, *gB, *gWp;
    cudaGetSymbolAddress((void**)&gQ, g_Q);
    cudaGetSymbolAddress((void**)&gK, g_K);
    cudaGetSymbolAddress((void**)&gV, g_V);
    cudaGetSymbolAddress((void**)&gA, g_A);
    cudaGetSymbolAddress((void**)&gB, g_B);
    cudaGetSymbolAddress((void**)&gWp, g_Wp);

    // 1. Fused projections (one wave)
    proj_kernel<<<dim3(6, 24), 256>>>(q, k, v, Wq, Wk, Wv, bq, bk, bv, gQ, gK, gV);

    // 2. A (mem·Q) and B (K·Q) scores
    scores_kernel<<<dim3(NH, 6), 256>>>(mem, gQ, gK, gA, gB);

    // 3. Fused T+W partials over 3 e-thirds
    wkfused_kernel<<<dim3(NH, 2, 3), 256>>>(gA, gB, gWp);

    // 4. out = (sum of W partials)^T @ V_h
    out_kernel<<<NH, 256>>>(gWp, gV, out);
}

// round 8
// speedup vs baseline: 2.4769x; 1.0947x over previous
#include <cuda_runtime.h>
#include <cuda_bf16.h>

// Problem constants
#define NN 4
#define QL 64
#define KL 64
#define DD 768
#define HH 16
#define HD 48
#define EE 300
#define NH (NN*HH)   // 64
#define ESPLIT 5     // e-chunks of 64

// Scratch (device globals — no allocation allowed). 128B-aligned for float4 access.
__device__ __align__(128) float g_Q[NN*QL*DD];          // [256][768]
__device__ __align__(128) float g_K[KL*DD];             // [64][768]
__device__ __align__(128) float g_V[KL*DD];             // [64][768]
__device__ __align__(128) float g_A[NH*EE*QL];          // [nh][e][q]
__device__ __align__(128) float g_B[NH*KL*QL];          // [nh][k][q]
__device__ __align__(128) float g_Wp[ESPLIT*NH*KL*QL];  // e-partials of [nh][k][q]

// ---------------------------------------------------------------------------
// Kernel 1: fused Q/K/V projections. Y = X @ Wt + bias
// grid (6 row-tiles, 24 col-tiles): rt 0-3 = Q tiles, 4 = K, 5 = V
// ---------------------------------------------------------------------------
__global__ __launch_bounds__(256) void proj_kernel(
    const float* __restrict__ qin, const float* __restrict__ kin,
    const float* __restrict__ vin,
    const float* __restrict__ Wq, const float* __restrict__ Wk,
    const float* __restrict__ Wv,
    const float* __restrict__ bq, const float* __restrict__ bk,
    const float* __restrict__ bv,
    float* __restrict__ Qo, float* __restrict__ Ko, float* __restrict__ Vo)
{
    __shared__ float As[32][64];   // [k][m] transposed (256B rows, float4-safe)
    __shared__ float Bs[32][34];   // [k][c] (136B rows, float2-safe)

    const int rt = blockIdx.x;
    const int c0 = blockIdx.y * 32;
    const float *X, *Wt, *bias;
    float* Y;
    if (rt < 4)      { X = qin + (size_t)rt * 64 * DD; Wt = Wq; bias = bq; Y = Qo + (size_t)rt * 64 * DD; }
    else if (rt == 4){ X = kin; Wt = Wk; bias = bk; Y = Ko; }
    else             { X = vin; Wt = Wv; bias = bv; Y = Vo; }

    const int tid = threadIdx.x;
    const int tx = tid & 15;       // col group (2 cols)
    const int ty = tid >> 4;       // row group (4 rows)
    const int lr = tid >> 2;       // A load row 0..63
    const int lc = (tid & 3) * 4;  // A load k-offset (and +16)
    const int br = tid >> 3;       // B load k-row 0..31
    const int bc = (tid & 7) * 4;  // B load col

    float acc[4][2];
#pragma unroll
    for (int i = 0; i < 4; i++) { acc[i][0] = 0.f; acc[i][1] = 0.f; }

    for (int k0 = 0; k0 < DD; k0 += 32) {
        const float4 a0 = *(const float4*)(X + (size_t)lr * DD + k0 + lc);
        const float4 a1 = *(const float4*)(X + (size_t)lr * DD + k0 + lc + 16);
        const float4 bb = *(const float4*)(Wt + (size_t)(k0 + br) * DD + c0 + bc);
        As[lc + 0][lr] = a0.x; As[lc + 1][lr] = a0.y;
        As[lc + 2][lr] = a0.z; As[lc + 3][lr] = a0.w;
        As[lc + 16][lr] = a1.x; As[lc + 17][lr] = a1.y;
        As[lc + 18][lr] = a1.z; As[lc + 19][lr] = a1.w;
        Bs[br][bc + 0] = bb.x; Bs[br][bc + 1] = bb.y;
        Bs[br][bc + 2] = bb.z; Bs[br][bc + 3] = bb.w;
        __syncthreads();
#pragma unroll
        for (int kk = 0; kk < 32; kk++) {
            const float4 a = *(const float4*)&As[kk][ty * 4];
            const float2 b = *(const float2*)&Bs[kk][tx * 2];
            acc[0][0] = fmaf(a.x, b.x, acc[0][0]); acc[0][1] = fmaf(a.x, b.y, acc[0][1]);
            acc[1][0] = fmaf(a.y, b.x, acc[1][0]); acc[1][1] = fmaf(a.y, b.y, acc[1][1]);
            acc[2][0] = fmaf(a.z, b.x, acc[2][0]); acc[2][1] = fmaf(a.z, b.y, acc[2][1]);
            acc[3][0] = fmaf(a.w, b.x, acc[3][0]); acc[3][1] = fmaf(a.w, b.y, acc[3][1]);
        }
        __syncthreads();
    }

    const float b0 = bias[c0 + tx * 2];
    const float b1 = bias[c0 + tx * 2 + 1];
#pragma unroll
    for (int i = 0; i < 4; i++) {
        float2 o = make_float2(acc[i][0] + b0, acc[i][1] + b1);
        *(float2*)(Y + (size_t)(ty * 4 + i) * DD + c0 + tx * 2) = o;
    }
}

// ---------------------------------------------------------------------------
// Kernel 2: per (n,h) scores
//   task<5 : A[nh][e][q] = sum_d mem[e,h,d] * Q[n,q,h,d]   (e-tile of 64)
//   task=5 : B[nh][k][q] = sum_d K[k,h,d]  * Q[n,q,h,d]
// ---------------------------------------------------------------------------
__global__ __launch_bounds__(256) void scores_kernel(
    const float* __restrict__ mem, const float* __restrict__ Q,
    const float* __restrict__ K, float* __restrict__ A, float* __restrict__ B)
{
    const int nh = blockIdx.x;          // 0..63
    const int n = nh >> 4, h = nh & 15;
    const int task = blockIdx.y;        // 0..4 = A e-tiles, 5 = B

    __shared__ float Ls[48][68];        // [d][r] (272B rows, float4-safe)
    __shared__ float Qs[48][68];        // [d][q]

    const int tid = threadIdx.x;
    const int r = tid >> 2;             // 0..63
    const int c = tid & 3;

    const float* lbase;
    int R;
    if (task < 5) { lbase = mem + (size_t)task * 64 * DD + h * HD; R = min(64, EE - task * 64); }
    else          { lbase = K + h * HD; R = 64; }

    {
        const float* srcL = lbase + (size_t)r * DD;
        const float* srcQ = Q + (size_t)(n * QL + r) * DD + h * HD;
#pragma unroll
        for (int j = 0; j < 3; j++) {
            const int d0 = c * 4 + j * 16;
            float4 vl = make_float4(0.f, 0.f, 0.f, 0.f);
            if (r < R) vl = *(const float4*)(srcL + d0);
            Ls[d0 + 0][r] = vl.x; Ls[d0 + 1][r] = vl.y;
            Ls[d0 + 2][r] = vl.z; Ls[d0 + 3][r] = vl.w;
            const float4 vq = *(const float4*)(srcQ + d0);
            Qs[d0 + 0][r] = vq.x; Qs[d0 + 1][r] = vq.y;
            Qs[d0 + 2][r] = vq.z; Qs[d0 + 3][r] = vq.w;
        }
    }
    __syncthreads();

    const int tx = tid & 15, ty = tid >> 4;
    float acc[4][4];
#pragma unroll
    for (int i = 0; i < 4; i++)
#pragma unroll
        for (int j = 0; j < 4; j++) acc[i][j] = 0.f;

#pragma unroll 8
    for (int d = 0; d < 48; d++) {
        const float4 a = *(const float4*)&Ls[d][ty * 4];
        const float4 b = *(const float4*)&Qs[d][tx * 4];
        acc[0][0] = fmaf(a.x, b.x, acc[0][0]); acc[0][1] = fmaf(a.x, b.y, acc[0][1]);
        acc[0][2] = fmaf(a.x, b.z, acc[0][2]); acc[0][3] = fmaf(a.x, b.w, acc[0][3]);
        acc[1][0] = fmaf(a.y, b.x, acc[1][0]); acc[1][1] = fmaf(a.y, b.y, acc[1][1]);
        acc[1][2] = fmaf(a.y, b.z, acc[1][2]); acc[1][3] = fmaf(a.y, b.w, acc[1][3]);
        acc[2][0] = fmaf(a.z, b.x, acc[2][0]); acc[2][1] = fmaf(a.z, b.y, acc[2][1]);
        acc[2][2] = fmaf(a.z, b.z, acc[2][2]); acc[2][3] = fmaf(a.z, b.w, acc[2][3]);
        acc[3][0] = fmaf(a.w, b.x, acc[3][0]); acc[3][1] = fmaf(a.w, b.y, acc[3][1]);
        acc[3][2] = fmaf(a.w, b.z, acc[3][2]); acc[3][3] = fmaf(a.w, b.w, acc[3][3]);
    }

    if (task < 5) {
        float* out = A + (size_t)nh * EE * QL;
#pragma unroll
        for (int i = 0; i < 4; i++) {
            int e = task * 64 + ty * 4 + i;
            if (e < EE) {
                float4 o = make_float4(acc[i][0], acc[i][1], acc[i][2], acc[i][3]);
                *(float4*)(out + (size_t)e * QL + tx * 4) = o;
            }
        }
    } else {
        float* out = B + (size_t)nh * KL * QL;
#pragma unroll
        for (int i = 0; i < 4; i++) {
            float4 o = make_float4(acc[i][0], acc[i][1], acc[i][2], acc[i][3]);
            *(float4*)(out + (size_t)(ty * 4 + i) * QL + tx * 4) = o;
        }
    }
}

// ---------------------------------------------------------------------------
// Kernel 3 (FUSED tsum+wk): one 64-e tile per block.
//   pass1: Tsh[e][k] = sum_q relu(A[e,q]+B[k,q]) (k local 0..31)
//   pass2: w[k,q] += relu(A[e,q]+B[k,q]) * Tsh[e][k]
// grid (64 nh, 2 k-halves of 32, 5 e-chunks of 64), 256 threads.
// Deterministic partials -> g_Wp; out_kernel sums the 5 buffers.
// ---------------------------------------------------------------------------
__global__ __launch_bounds__(256) void wkfused_kernel(
    const float* __restrict__ A, const float* __restrict__ B,
    float* __restrict__ Wp)
{
    const int nh = blockIdx.x;
    const int kg = blockIdx.y;          // 0,1
    const int es = blockIdx.z;          // 0..4
    const int e0 = es * 64;
    const int ec = min(64, EE - e0);    // 64,64,64,64,44

    __shared__ float Ash[64][64];       // [e][q] (256B rows, float4-safe)
    __shared__ float Bsh[32][66];       // [k-local][q] (264B rows, float2-safe)
    __shared__ float Tsh[64][32];       // [e][k-local]

    const int tid = threadIdx.x;
    const int qx = tid & 15;            // pass2: q4 = qx*4
    const int ky = tid >> 4;            // pass2: local k pair = ky*2, ky*2+1
    const int kp = tid & 31;            // pass1: local k
    const int eb = tid >> 5;            // pass1: warp -> e group of 8

    const float* Bb = B + ((size_t)nh * KL + kg * 32) * QL;

    // load Bsh (32 x 64)
#pragma unroll
    for (int i = 0; i < 2; i++) {
        int f = tid + i * 256;
        int k = f >> 4, qq = (f & 15) * 4;
        float4 v = *(const float4*)(Bb + (size_t)k * QL + qq);
        Bsh[k][qq + 0] = v.x; Bsh[k][qq + 1] = v.y;
        Bsh[k][qq + 2] = v.z; Bsh[k][qq + 3] = v.w;
    }

    // pass2 per-thread B registers
    const float4 b0 = *(const float4*)(Bb + (size_t)(ky * 2) * QL + qx * 4);
    const float4 b1 = *(const float4*)(Bb + (size_t)(ky * 2 + 1) * QL + qx * 4);

    float4 w0 = make_float4(0.f, 0.f, 0.f, 0.f);
    float4 w1 = make_float4(0.f, 0.f, 0.f, 0.f);

    const float* Ab = A + (size_t)nh * EE * QL;

    // load A tile: 4 float4/thread (zero-pad beyond ec)
#pragma unroll
    for (int i = 0; i < 4; i++) {
        int f = tid + i * 256;
        int e = f >> 4, qq = (f & 15) * 4;
        float4 v = make_float4(0.f, 0.f, 0.f, 0.f);
        if (e < ec) v = *(const float4*)(Ab + (size_t)(e0 + e) * QL + qq);
        *(float4*)&Ash[e][qq] = v;
    }
    __syncthreads();

    // pass1: each thread sums 8 e rows (e = eb*8 + i) over all 64 q
    {
        float tacc[8];
#pragma unroll
        for (int i = 0; i < 8; i++) tacc[i] = 0.f;
#pragma unroll 4
        for (int q2 = 0; q2 < 32; q2++) {
            const float2 b = *(const float2*)&Bsh[kp][q2 * 2];
#pragma unroll
            for (int i = 0; i < 8; i++) {
                const float2 a = *(const float2*)&Ash[eb * 8 + i][q2 * 2];
                tacc[i] += fmaxf(a.x + b.x, 0.f) + fmaxf(a.y + b.y, 0.f);
            }
        }
#pragma unroll
        for (int i = 0; i < 8; i++) {
            const int e = eb * 8 + i;
            Tsh[e][kp] = (e < ec) ? tacc[i] : 0.f;  // zero padded rows
        }
    }
    __syncthreads();

    // pass2: microtile accumulate
#pragma unroll 8
    for (int e = 0; e < 64; e++) {
        const float4 a = *(const float4*)&Ash[e][qx * 4];
        const float2 t = *(const float2*)&Tsh[e][ky * 2];
        float s;
        s = fmaxf(a.x + b0.x, 0.f); w0.x = fmaf(t.x, s, w0.x);
        s = fmaxf(a.y + b0.y, 0.f); w0.y = fmaf(t.x, s, w0.y);
        s = fmaxf(a.z + b0.z, 0.f); w0.z = fmaf(t.x, s, w0.z);
        s = fmaxf(a.w + b0.w, 0.f); w0.w = fmaf(t.x, s, w0.w);
        s = fmaxf(a.x + b1.x, 0.f); w1.x = fmaf(t.y, s, w1.x);
        s = fmaxf(a.y + b1.y, 0.f); w1.y = fmaf(t.y, s, w1.y);
        s = fmaxf(a.z + b1.z, 0.f); w1.z = fmaf(t.y, s, w1.z);
        s = fmaxf(a.w + b1.w, 0.f); w1.w = fmaf(t.y, s, w1.w);
    }

    float* Wb = Wp + ((size_t)es * NH + nh) * KL * QL + (size_t)kg * 32 * QL;
    *(float4*)(Wb + (size_t)(ky * 2) * QL + qx * 4)     = w0;
    *(float4*)(Wb + (size_t)(ky * 2 + 1) * QL + qx * 4) = w1;
}

// ---------------------------------------------------------------------------
// Kernel 4: out[n,q,h,d] = sum_k (sum_es Wp[es])[nh][k][q] * V[k,h,d]
// grid (64 nh, 4 q-quarters of 16), 256 threads.
// ---------------------------------------------------------------------------
__global__ __launch_bounds__(256) void out_kernel(
    const float* __restrict__ Wp, const float* __restrict__ V, float* __restrict__ out)
{
    const int nh = blockIdx.x;
    const int qy = blockIdx.y;          // q quarter
    const int n = nh >> 4, h = nh & 15;
    const int q0 = qy * 16;

    __shared__ float Ws[64][16];   // [k][q-local] (64B rows, float4-safe)
    __shared__ float Vs[64][48];   // [k][d] (192B rows, float4-safe)

    const int tid = threadIdx.x;
    const float* Wb = Wp + (size_t)nh * KL * QL + q0;

    // Ws: 1024 floats = 1 float4/thread, summing ESPLIT partials
    {
        int k = tid >> 2, qq = (tid & 3) * 4;
        const float* p = Wb + (size_t)k * QL + qq;
        float4 s = make_float4(0.f, 0.f, 0.f, 0.f);
#pragma unroll
        for (int es = 0; es < ESPLIT; es++) {
            const float4 v = *(const float4*)(p + (size_t)es * NH * KL * QL);
            s.x += v.x; s.y += v.y; s.z += v.z; s.w += v.w;
        }
        *(float4*)&Ws[k][qq] = s;
    }
    // Vs: 3072 floats = 3 float4/thread
#pragma unroll
    for (int i = 0; i < 3; i++) {
        int f = tid + i * 256;
        int k = f / 12, d4 = (f % 12) * 4;
        const float4 v = *(const float4*)(V + (size_t)k * DD + h * HD + d4);
        *(float4*)&Vs[k][d4] = v;
    }
    __syncthreads();

    const int tx = tid & 15;      // d group of 3
    const int ty = tid >> 4;      // q local (1 each)
    float acc[3] = {0.f, 0.f, 0.f};

#pragma unroll 8
    for (int kk = 0; kk < 64; kk++) {
        const float wq = Ws[kk][ty];
        acc[0] = fmaf(wq, Vs[kk][tx * 3 + 0], acc[0]);
        acc[1] = fmaf(wq, Vs[kk][tx * 3 + 1], acc[1]);
        acc[2] = fmaf(wq, Vs[kk][tx * 3 + 2], acc[2]);
    }

    const int q = q0 + ty;
#pragma unroll
    for (int j = 0; j < 3; j++)
        out[(size_t)(n * QL + q) * DD + h * HD + tx * 3 + j] = acc[j];
}

// ---------------------------------------------------------------------------
// Launch
// Inputs: 0=q 1=k 2=v 3=Wq 4=bq 5=Wk 6=bk 7=Wv 8=bv 9=memory
// ---------------------------------------------------------------------------
extern "C" void kernel_launch(void* const* d_in, const int* in_sizes, int n_in,
                              void* d_out, int out_size)
{
    const float* q   = (const float*)d_in[0];
    const float* k   = (const float*)d_in[1];
    const float* v   = (const float*)d_in[2];
    const float* Wq  = (const float*)d_in[3];
    const float* bq  = (const float*)d_in[4];
    const float* Wk  = (const float*)d_in[5];
    const float* bk  = (const float*)d_in[6];
    const float* Wv  = (const float*)d_in[7];
    const float* bv  = (const float*)d_in[8];
    const float* mem = (const float*)d_in[9];
    float* out = (float*)d_out;

    float *gQ, *gK, *gV, *gA, *gB, *gWp;
    cudaGetSymbolAddress((void**)&gQ, g_Q);
    cudaGetSymbolAddress((void**)&gK, g_K);
    cudaGetSymbolAddress((void**)&gV, g_V);
    cudaGetSymbolAddress((void**)&gA, g_A);
    cudaGetSymbolAddress((void**)&gB, g_B);
    cudaGetSymbolAddress((void**)&gWp, g_Wp);

    // 1. Fused projections (one wave)
    proj_kernel<<<dim3(6, 24), 256>>>(q, k, v, Wq, Wk, Wv, bq, bk, bv, gQ, gK, gV);

    // 2. A (mem·Q) and B (K·Q) scores
    scores_kernel<<<dim3(NH, 6), 256>>>(mem, gQ, gK, gA, gB);

    // 3. Fused T+W partials over 5 e-chunks (640 blocks)
    wkfused_kernel<<<dim3(NH, 2, ESPLIT), 256>>>(gA, gB, gWp);

    // 4. out = (sum of W partials)^T @ V_h (256 blocks)
    out_kernel<<<dim3(NH, 4), 256>>>(gWp, gV, out);
}

// round 9
// speedup vs baseline: 2.5026x; 1.0104x over previous
#include <cuda_runtime.h>
#include <cuda_bf16.h>

// Problem constants
#define NN 4
#define QL 64
#define KL 64
#define DD 768
#define HH 16
#define HD 48
#define EE 300
#define NH (NN*HH)   // 64
#define ESPLIT 5     // e-chunks of 64

typedef unsigned long long ull;

// Packed fp32x2 helpers (SASS FADD2/FFMA2; numerics identical to 2x scalar rn)
#define PK2(d, lo, hi)    asm("mov.b64 %0, {%1, %2};" : "=l"(d) : "f"(lo), "f"(hi))
#define UPK2(lo, hi, s)   asm("mov.b64 {%0, %1}, %2;" : "=f"(lo), "=f"(hi) : "l"(s))
#define FADD2(d, a, b)    asm("add.rn.f32x2 %0, %1, %2;" : "=l"(d) : "l"(a), "l"(b))
#define FFMA2(d, a, b, c) asm("fma.rn.f32x2 %0, %1, %2, %3;" : "=l"(d) : "l"(a), "l"(b), "l"(c))

__device__ __forceinline__ ull relu2(ull p) {
    float x, y; UPK2(x, y, p);
    x = fmaxf(x, 0.f); y = fmaxf(y, 0.f);
    ull r; PK2(r, x, y); return r;
}

// Scratch (device globals — no allocation allowed). 128B-aligned for float4 access.
__device__ __align__(128) float g_Q[NN*QL*DD];          // [256][768]
__device__ __align__(128) float g_K[KL*DD];             // [64][768]
__device__ __align__(128) float g_V[KL*DD];             // [64][768]
__device__ __align__(128) float g_A[NH*EE*QL];          // [nh][e][q]
__device__ __align__(128) float g_B[NH*KL*QL];          // [nh][k][q]
__device__ __align__(128) float g_Wp[ESPLIT*NH*KL*QL];  // e-partials of [nh][k][q]

// ---------------------------------------------------------------------------
// Kernel 1: fused Q/K/V projections. Y = X @ Wt + bias (f32x2 inner loop)
// grid (6 row-tiles, 24 col-tiles): rt 0-3 = Q tiles, 4 = K, 5 = V
// ---------------------------------------------------------------------------
__global__ __launch_bounds__(256) void proj_kernel(
    const float* __restrict__ qin, const float* __restrict__ kin,
    const float* __restrict__ vin,
    const float* __restrict__ Wq, const float* __restrict__ Wk,
    const float* __restrict__ Wv,
    const float* __restrict__ bq, const float* __restrict__ bk,
    const float* __restrict__ bv,
    float* __restrict__ Qo, float* __restrict__ Ko, float* __restrict__ Vo)
{
    __shared__ float As[32][64];   // [k][m] transposed (256B rows, float4-safe)
    __shared__ float Bs[32][34];   // [k][c] (136B rows, float2-safe)

    const int rt = blockIdx.x;
    const int c0 = blockIdx.y * 32;
    const float *X, *Wt, *bias;
    float* Y;
    if (rt < 4)      { X = qin + (size_t)rt * 64 * DD; Wt = Wq; bias = bq; Y = Qo + (size_t)rt * 64 * DD; }
    else if (rt == 4){ X = kin; Wt = Wk; bias = bk; Y = Ko; }
    else             { X = vin; Wt = Wv; bias = bv; Y = Vo; }

    const int tid = threadIdx.x;
    const int tx = tid & 15;       // col group (2 cols)
    const int ty = tid >> 4;       // row group (4 rows)
    const int lr = tid >> 2;       // A load row 0..63
    const int lc = (tid & 3) * 4;  // A load k-offset (and +16)
    const int br = tid >> 3;       // B load k-row 0..31
    const int bc = (tid & 7) * 4;  // B load col

    // accp[j][p]: j = output col (0,1), p = row pair (rows 2p,2p+1 of microtile)
    ull accp[2][2] = {{0ull, 0ull}, {0ull, 0ull}};

    for (int k0 = 0; k0 < DD; k0 += 32) {
        const float4 a0 = *(const float4*)(X + (size_t)lr * DD + k0 + lc);
        const float4 a1 = *(const float4*)(X + (size_t)lr * DD + k0 + lc + 16);
        const float4 bb = *(const float4*)(Wt + (size_t)(k0 + br) * DD + c0 + bc);
        As[lc + 0][lr] = a0.x; As[lc + 1][lr] = a0.y;
        As[lc + 2][lr] = a0.z; As[lc + 3][lr] = a0.w;
        As[lc + 16][lr] = a1.x; As[lc + 17][lr] = a1.y;
        As[lc + 18][lr] = a1.z; As[lc + 19][lr] = a1.w;
        Bs[br][bc + 0] = bb.x; Bs[br][bc + 1] = bb.y;
        Bs[br][bc + 2] = bb.z; Bs[br][bc + 3] = bb.w;
        __syncthreads();
#pragma unroll
        for (int kk = 0; kk < 32; kk++) {
            const float4 a = *(const float4*)&As[kk][ty * 4];
            const float2 b = *(const float2*)&Bs[kk][tx * 2];
            const ull a01 = ((const ull*)&a)[0];
            const ull a23 = ((const ull*)&a)[1];
            ull bx2, by2; PK2(bx2, b.x, b.x); PK2(by2, b.y, b.y);
            FFMA2(accp[0][0], a01, bx2, accp[0][0]);
            FFMA2(accp[0][1], a23, bx2, accp[0][1]);
            FFMA2(accp[1][0], a01, by2, accp[1][0]);
            FFMA2(accp[1][1], a23, by2, accp[1][1]);
        }
        __syncthreads();
    }

    const float b0 = bias[c0 + tx * 2];
    const float b1 = bias[c0 + tx * 2 + 1];
    float c00, c10, c20, c30, c01, c11, c21, c31;
    UPK2(c00, c10, accp[0][0]); UPK2(c20, c30, accp[0][1]);
    UPK2(c01, c11, accp[1][0]); UPK2(c21, c31, accp[1][1]);
    float cj0[4] = {c00, c10, c20, c30};
    float cj1[4] = {c01, c11, c21, c31};
#pragma unroll
    for (int i = 0; i < 4; i++) {
        float2 o = make_float2(cj0[i] + b0, cj1[i] + b1);
        *(float2*)(Y + (size_t)(ty * 4 + i) * DD + c0 + tx * 2) = o;
    }
}

// ---------------------------------------------------------------------------
// Kernel 2: per (n,h) scores (f32x2 inner loop)
//   task<5 : A[nh][e][q] = sum_d mem[e,h,d] * Q[n,q,h,d]   (e-tile of 64)
//   task=5 : B[nh][k][q] = sum_d K[k,h,d]  * Q[n,q,h,d]
// ---------------------------------------------------------------------------
__global__ __launch_bounds__(256) void scores_kernel(
    const float* __restrict__ mem, const float* __restrict__ Q,
    const float* __restrict__ K, float* __restrict__ A, float* __restrict__ B)
{
    const int nh = blockIdx.x;          // 0..63
    const int n = nh >> 4, h = nh & 15;
    const int task = blockIdx.y;        // 0..4 = A e-tiles, 5 = B

    __shared__ float Ls[48][68];        // [d][r] (272B rows, float4-safe)
    __shared__ float Qs[48][68];        // [d][q]

    const int tid = threadIdx.x;
    const int r = tid >> 2;             // 0..63
    const int c = tid & 3;

    const float* lbase;
    int R;
    if (task < 5) { lbase = mem + (size_t)task * 64 * DD + h * HD; R = min(64, EE - task * 64); }
    else          { lbase = K + h * HD; R = 64; }

    {
        const float* srcL = lbase + (size_t)r * DD;
        const float* srcQ = Q + (size_t)(n * QL + r) * DD + h * HD;
#pragma unroll
        for (int j = 0; j < 3; j++) {
            const int d0 = c * 4 + j * 16;
            float4 vl = make_float4(0.f, 0.f, 0.f, 0.f);
            if (r < R) vl = *(const float4*)(srcL + d0);
            Ls[d0 + 0][r] = vl.x; Ls[d0 + 1][r] = vl.y;
            Ls[d0 + 2][r] = vl.z; Ls[d0 + 3][r] = vl.w;
            const float4 vq = *(const float4*)(srcQ + d0);
            Qs[d0 + 0][r] = vq.x; Qs[d0 + 1][r] = vq.y;
            Qs[d0 + 2][r] = vq.z; Qs[d0 + 3][r] = vq.w;
        }
    }
    __syncthreads();

    const int tx = tid & 15, ty = tid >> 4;
    // accp[i][jp]: i = L-row of microtile, jp = q col pair (cols 2jp,2jp+1)
    ull accp[4][2];
#pragma unroll
    for (int i = 0; i < 4; i++) { accp[i][0] = 0ull; accp[i][1] = 0ull; }

#pragma unroll 8
    for (int d = 0; d < 48; d++) {
        const float4 a = *(const float4*)&Ls[d][ty * 4];
        const float4 b = *(const float4*)&Qs[d][tx * 4];
        const ull b01 = ((const ull*)&b)[0];
        const ull b23 = ((const ull*)&b)[1];
        ull ax2, ay2, az2, aw2;
        PK2(ax2, a.x, a.x); PK2(ay2, a.y, a.y);
        PK2(az2, a.z, a.z); PK2(aw2, a.w, a.w);
        FFMA2(accp[0][0], b01, ax2, accp[0][0]); FFMA2(accp[0][1], b23, ax2, accp[0][1]);
        FFMA2(accp[1][0], b01, ay2, accp[1][0]); FFMA2(accp[1][1], b23, ay2, accp[1][1]);
        FFMA2(accp[2][0], b01, az2, accp[2][0]); FFMA2(accp[2][1], b23, az2, accp[2][1]);
        FFMA2(accp[3][0], b01, aw2, accp[3][0]); FFMA2(accp[3][1], b23, aw2, accp[3][1]);
    }

    if (task < 5) {
        float* out = A + (size_t)nh * EE * QL;
#pragma unroll
        for (int i = 0; i < 4; i++) {
            int e = task * 64 + ty * 4 + i;
            if (e < EE) {
                float4 o;
                UPK2(o.x, o.y, accp[i][0]); UPK2(o.z, o.w, accp[i][1]);
                *(float4*)(out + (size_t)e * QL + tx * 4) = o;
            }
        }
    } else {
        float* out = B + (size_t)nh * KL * QL;
#pragma unroll
        for (int i = 0; i < 4; i++) {
            float4 o;
            UPK2(o.x, o.y, accp[i][0]); UPK2(o.z, o.w, accp[i][1]);
            *(float4*)(out + (size_t)(ty * 4 + i) * QL + tx * 4) = o;
        }
    }
}

// ---------------------------------------------------------------------------
// Kernel 3 (FUSED tsum+wk, f32x2): one 64-e tile per block.
//   pass1: Tsh[e][k] = sum_q relu(A[e,q]+B[k,q]) (k local 0..31)
//   pass2: w[k,q] += relu(A[e,q]+B[k,q]) * Tsh[e][k]
// grid (64 nh, 2 k-halves of 32, 5 e-chunks of 64), 256 threads.
// ---------------------------------------------------------------------------
__global__ __launch_bounds__(256) void wkfused_kernel(
    const float* __restrict__ A, const float* __restrict__ B,
    float* __restrict__ Wp)
{
    const int nh = blockIdx.x;
    const int kg = blockIdx.y;          // 0,1
    const int es = blockIdx.z;          // 0..4
    const int e0 = es * 64;
    const int ec = min(64, EE - e0);    // 64,64,64,64,44

    __shared__ float Ash[64][64];       // [e][q] (256B rows, float4-safe)
    __shared__ float Bsh[32][66];       // [k-local][q] (264B rows, ull-safe)
    __shared__ float Tsh[64][32];       // [e][k-local] (128B rows)

    const int tid = threadIdx.x;
    const int qx = tid & 15;            // pass2: q4 = qx*4
    const int ky = tid >> 4;            // pass2: local k pair = ky*2, ky*2+1
    const int kp = tid & 31;            // pass1: local k
    const int eb = tid >> 5;            // pass1: warp -> e group of 8

    const float* Bb = B + ((size_t)nh * KL + kg * 32) * QL;

    // load Bsh (32 x 64)
#pragma unroll
    for (int i = 0; i < 2; i++) {
        int f = tid + i * 256;
        int k = f >> 4, qq = (f & 15) * 4;
        float4 v = *(const float4*)(Bb + (size_t)k * QL + qq);
        Bsh[k][qq + 0] = v.x; Bsh[k][qq + 1] = v.y;
        Bsh[k][qq + 2] = v.z; Bsh[k][qq + 3] = v.w;
    }

    // pass2 per-thread B registers (as packed pairs)
    const float4 b0 = *(const float4*)(Bb + (size_t)(ky * 2) * QL + qx * 4);
    const float4 b1 = *(const float4*)(Bb + (size_t)(ky * 2 + 1) * QL + qx * 4);
    const ull b0a = ((const ull*)&b0)[0], b0b = ((const ull*)&b0)[1];
    const ull b1a = ((const ull*)&b1)[0], b1b = ((const ull*)&b1)[1];

    ull w0a = 0ull, w0b = 0ull, w1a = 0ull, w1b = 0ull;

    const float* Ab = A + (size_t)nh * EE * QL;

    // load A tile: 4 float4/thread (zero-pad beyond ec)
#pragma unroll
    for (int i = 0; i < 4; i++) {
        int f = tid + i * 256;
        int e = f >> 4, qq = (f & 15) * 4;
        float4 v = make_float4(0.f, 0.f, 0.f, 0.f);
        if (e < ec) v = *(const float4*)(Ab + (size_t)(e0 + e) * QL + qq);
        *(float4*)&Ash[e][qq] = v;
    }
    __syncthreads();

    // pass1: each thread sums 8 e rows (e = eb*8 + i) over all 64 q (packed q pairs)
    {
        ull tacc2[8];
#pragma unroll
        for (int i = 0; i < 8; i++) tacc2[i] = 0ull;
#pragma unroll 4
        for (int q2 = 0; q2 < 32; q2++) {
            const ull b2 = *(const ull*)&Bsh[kp][q2 * 2];
#pragma unroll
            for (int i = 0; i < 8; i++) {
                const ull a2 = *(const ull*)&Ash[eb * 8 + i][q2 * 2];
                ull p; FADD2(p, a2, b2);
                p = relu2(p);
                FADD2(tacc2[i], tacc2[i], p);
            }
        }
#pragma unroll
        for (int i = 0; i < 8; i++) {
            const int e = eb * 8 + i;
            float x, y; UPK2(x, y, tacc2[i]);
            Tsh[e][kp] = (e < ec) ? (x + y) : 0.f;  // zero padded rows
        }
    }
    __syncthreads();

    // pass2: microtile accumulate (packed)
#pragma unroll 8
    for (int e = 0; e < 64; e++) {
        const float4 a = *(const float4*)&Ash[e][qx * 4];
        const ull a01 = ((const ull*)&a)[0];
        const ull a23 = ((const ull*)&a)[1];
        const float2 t = *(const float2*)&Tsh[e][ky * 2];
        ull tx2, ty2; PK2(tx2, t.x, t.x); PK2(ty2, t.y, t.y);
        ull p;
        FADD2(p, a01, b0a); p = relu2(p); FFMA2(w0a, p, tx2, w0a);
        FADD2(p, a23, b0b); p = relu2(p); FFMA2(w0b, p, tx2, w0b);
        FADD2(p, a01, b1a); p = relu2(p); FFMA2(w1a, p, ty2, w1a);
        FADD2(p, a23, b1b); p = relu2(p); FFMA2(w1b, p, ty2, w1b);
    }

    float4 w0, w1;
    UPK2(w0.x, w0.y, w0a); UPK2(w0.z, w0.w, w0b);
    UPK2(w1.x, w1.y, w1a); UPK2(w1.z, w1.w, w1b);

    float* Wb = Wp + ((size_t)es * NH + nh) * KL * QL + (size_t)kg * 32 * QL;
    *(float4*)(Wb + (size_t)(ky * 2) * QL + qx * 4)     = w0;
    *(float4*)(Wb + (size_t)(ky * 2 + 1) * QL + qx * 4) = w1;
}

// ---------------------------------------------------------------------------
// Kernel 4: out[n,q,h,d] = sum_k (sum_es Wp[es])[nh][k][q] * V[k,h,d]
// grid (64 nh, 8 q-octets), 128 threads.
// ---------------------------------------------------------------------------
__global__ __launch_bounds__(128) void out_kernel(
    const float* __restrict__ Wp, const float* __restrict__ V, float* __restrict__ out)
{
    const int nh = blockIdx.x;
    const int qy = blockIdx.y;          // q octet
    const int n = nh >> 4, h = nh & 15;
    const int q0 = qy * 8;

    __shared__ float Ws[64][8];    // [k][q-local] (32B rows, float4-safe)
    __shared__ float Vs[64][48];   // [k][d] (192B rows, float4-safe)

    const int tid = threadIdx.x;   // 0..127
    const float* Wb = Wp + (size_t)nh * KL * QL + q0;

    // Ws: 512 floats = 1 float4/thread, summing ESPLIT partials
    {
        int k = tid >> 1, qq = (tid & 1) * 4;
        const float* p = Wb + (size_t)k * QL + qq;
        float4 s = make_float4(0.f, 0.f, 0.f, 0.f);
#pragma unroll
        for (int es = 0; es < ESPLIT; es++) {
            const float4 v = *(const float4*)(p + (size_t)es * NH * KL * QL);
            s.x += v.x; s.y += v.y; s.z += v.z; s.w += v.w;
        }
        *(float4*)&Ws[k][qq] = s;
    }
    // Vs: 3072 floats = 6 float4/thread
#pragma unroll
    for (int i = 0; i < 6; i++) {
        int f = tid + i * 128;
        int k = f / 12, d4 = (f % 12) * 4;
        const float4 v = *(const float4*)(V + (size_t)k * DD + h * HD + d4);
        *(float4*)&Vs[k][d4] = v;
    }
    __syncthreads();

    const int tx = tid & 15;      // d group of 3
    const int ty = tid >> 4;      // q local 0..7
    float acc[3] = {0.f, 0.f, 0.f};

#pragma unroll 8
    for (int kk = 0; kk < 64; kk++) {
        const float wq = Ws[kk][ty];
        acc[0] = fmaf(wq, Vs[kk][tx * 3 + 0], acc[0]);
        acc[1] = fmaf(wq, Vs[kk][tx * 3 + 1], acc[1]);
        acc[2] = fmaf(wq, Vs[kk][tx * 3 + 2], acc[2]);
    }

    const int q = q0 + ty;
#pragma unroll
    for (int j = 0; j < 3; j++)
        out[(size_t)(n * QL + q) * DD + h * HD + tx * 3 + j] = acc[j];
}

// ---------------------------------------------------------------------------
// Launch
// Inputs: 0=q 1=k 2=v 3=Wq 4=bq 5=Wk 6=bk 7=Wv 8=bv 9=memory
// ---------------------------------------------------------------------------
extern "C" void kernel_launch(void* const* d_in, const int* in_sizes, int n_in,
                              void* d_out, int out_size)
{
    const float* q   = (const float*)d_in[0];
    const float* k   = (const float*)d_in[1];
    const float* v   = (const float*)d_in[2];
    const float* Wq  = (const float*)d_in[3];
    const float* bq  = (const float*)d_in[4];
    const float* Wk  = (const float*)d_in[5];
    const float* bk  = (const float*)d_in[6];
    const float* Wv  = (const float*)d_in[7];
    const float* bv  = (const float*)d_in[8];
    const float* mem = (const float*)d_in[9];
    float* out = (float*)d_out;

    float *gQ, *gK, *gV, *gA, *gB, *gWp;
    cudaGetSymbolAddress((void**)&gQ, g_Q);
    cudaGetSymbolAddress((void**)&gK, g_K);
    cudaGetSymbolAddress((void**)&gV, g_V);
    cudaGetSymbolAddress((void**)&gA, g_A);
    cudaGetSymbolAddress((void**)&gB, g_B);
    cudaGetSymbolAddress((void**)&gWp, g_Wp);

    // 1. Fused projections (one wave)
    proj_kernel<<<dim3(6, 24), 256>>>(q, k, v, Wq, Wk, Wv, bq, bk, bv, gQ, gK, gV);

    // 2. A (mem·Q) and B (K·Q) scores
    scores_kernel<<<dim3(NH, 6), 256>>>(mem, gQ, gK, gA, gB);

    // 3. Fused T+W partials over 5 e-chunks (640 blocks)
    wkfused_kernel<<<dim3(NH, 2, ESPLIT), 256>>>(gA, gB, gWp);

    // 4. out = (sum of W partials)^T @ V_h (512 blocks)
    out_kernel<<<dim3(NH, 8), 128>>>(gWp, gV, out);
}

// round 10
// speedup vs baseline: 2.7499x; 1.0988x over previous
#include <cuda_runtime.h>
#include <cuda_bf16.h>

// Problem constants
#define NN 4
#define QL 64
#define KL 64
#define DD 768
#define HH 16
#define HD 48
#define EE 300
#define NH (NN*HH)   // 64
#define ESPLIT 5     // e-chunks of 64

typedef unsigned long long ull;

// Packed fp32x2 helpers (SASS FADD2/FFMA2; numerics identical to 2x scalar rn)
#define PK2(d, lo, hi)    asm("mov.b64 %0, {%1, %2};" : "=l"(d) : "f"(lo), "f"(hi))
#define UPK2(lo, hi, s)   asm("mov.b64 {%0, %1}, %2;" : "=f"(lo), "=f"(hi) : "l"(s))
#define FADD2(d, a, b)    asm("add.rn.f32x2 %0, %1, %2;" : "=l"(d) : "l"(a), "l"(b))
#define FFMA2(d, a, b, c) asm("fma.rn.f32x2 %0, %1, %2, %3;" : "=l"(d) : "l"(a), "l"(b), "l"(c))

__device__ __forceinline__ ull relu2(ull p) {
    float x, y; UPK2(x, y, p);
    x = fmaxf(x, 0.f); y = fmaxf(y, 0.f);
    ull r; PK2(r, x, y); return r;
}

// Scratch (device globals — no allocation allowed). 128B-aligned for float4 access.
// Q/K/V hold TWO k-halves (proj k-split); consumers sum halves during staging.
__device__ __align__(128) float g_Q[2*NN*QL*DD];
__device__ __align__(128) float g_K[2*KL*DD];
__device__ __align__(128) float g_V[2*KL*DD];
__device__ __align__(128) float g_A[NH*EE*QL];          // [nh][e][q]
__device__ __align__(128) float g_B[NH*KL*QL];          // [nh][k][q]
__device__ __align__(128) float g_Wp[ESPLIT*NH*KL*QL];  // e-partials of [nh][k][q]

// ---------------------------------------------------------------------------
// Kernel 1: fused Q/K/V projections, k-split in 2 halves.
// grid (6 row-tiles, 24 col-tiles, 2 k-halves). Half ks computes
// X[:, ks*384:+384] @ W[ks*384:+384, :]; bias only in half 0.
// ---------------------------------------------------------------------------
__global__ __launch_bounds__(256) void proj_kernel(
    const float* __restrict__ qin, const float* __restrict__ kin,
    const float* __restrict__ vin,
    const float* __restrict__ Wq, const float* __restrict__ Wk,
    const float* __restrict__ Wv,
    const float* __restrict__ bq, const float* __restrict__ bk,
    const float* __restrict__ bv,
    float* __restrict__ Qo, float* __restrict__ Ko, float* __restrict__ Vo)
{
    __shared__ float As[32][64];   // [k][m] transposed (256B rows, float4-safe)
    __shared__ float Bs[32][34];   // [k][c] (136B rows, float2-safe)

    const int rt = blockIdx.x;
    const int c0 = blockIdx.y * 32;
    const int ks = blockIdx.z;          // k half
    const int kbase = ks * (DD / 2);
    const float *X, *Wt, *bias;
    float* Y;
    if (rt < 4)      { X = qin + (size_t)rt * 64 * DD; Wt = Wq; bias = bq;
                       Y = Qo + (size_t)ks * NN * QL * DD + (size_t)rt * 64 * DD; }
    else if (rt == 4){ X = kin; Wt = Wk; bias = bk; Y = Ko + (size_t)ks * KL * DD; }
    else             { X = vin; Wt = Wv; bias = bv; Y = Vo + (size_t)ks * KL * DD; }

    const int tid = threadIdx.x;
    const int tx = tid & 15;       // col group (2 cols)
    const int ty = tid >> 4;       // row group (4 rows)
    const int lr = tid >> 2;       // A load row 0..63
    const int lc = (tid & 3) * 4;  // A load k-offset (and +16)
    const int br = tid >> 3;       // B load k-row 0..31
    const int bc = (tid & 7) * 4;  // B load col

    // accp[j][p]: j = output col (0,1), p = row pair (rows 2p,2p+1 of microtile)
    ull accp[2][2] = {{0ull, 0ull}, {0ull, 0ull}};

    for (int k0 = kbase; k0 < kbase + DD / 2; k0 += 32) {
        const float4 a0 = *(const float4*)(X + (size_t)lr * DD + k0 + lc);
        const float4 a1 = *(const float4*)(X + (size_t)lr * DD + k0 + lc + 16);
        const float4 bb = *(const float4*)(Wt + (size_t)(k0 + br) * DD + c0 + bc);
        As[lc + 0][lr] = a0.x; As[lc + 1][lr] = a0.y;
        As[lc + 2][lr] = a0.z; As[lc + 3][lr] = a0.w;
        As[lc + 16][lr] = a1.x; As[lc + 17][lr] = a1.y;
        As[lc + 18][lr] = a1.z; As[lc + 19][lr] = a1.w;
        Bs[br][bc + 0] = bb.x; Bs[br][bc + 1] = bb.y;
        Bs[br][bc + 2] = bb.z; Bs[br][bc + 3] = bb.w;
        __syncthreads();
#pragma unroll
        for (int kk = 0; kk < 32; kk++) {
            const float4 a = *(const float4*)&As[kk][ty * 4];
            const float2 b = *(const float2*)&Bs[kk][tx * 2];
            const ull a01 = ((const ull*)&a)[0];
            const ull a23 = ((const ull*)&a)[1];
            ull bx2, by2; PK2(bx2, b.x, b.x); PK2(by2, b.y, b.y);
            FFMA2(accp[0][0], a01, bx2, accp[0][0]);
            FFMA2(accp[0][1], a23, bx2, accp[0][1]);
            FFMA2(accp[1][0], a01, by2, accp[1][0]);
            FFMA2(accp[1][1], a23, by2, accp[1][1]);
        }
        __syncthreads();
    }

    const float b0 = (ks == 0) ? bias[c0 + tx * 2]     : 0.f;
    const float b1 = (ks == 0) ? bias[c0 + tx * 2 + 1] : 0.f;
    float c00, c10, c20, c30, c01, c11, c21, c31;
    UPK2(c00, c10, accp[0][0]); UPK2(c20, c30, accp[0][1]);
    UPK2(c01, c11, accp[1][0]); UPK2(c21, c31, accp[1][1]);
    float cj0[4] = {c00, c10, c20, c30};
    float cj1[4] = {c01, c11, c21, c31};
#pragma unroll
    for (int i = 0; i < 4; i++) {
        float2 o = make_float2(cj0[i] + b0, cj1[i] + b1);
        *(float2*)(Y + (size_t)(ty * 4 + i) * DD + c0 + tx * 2) = o;
    }
}

// ---------------------------------------------------------------------------
// Kernel 2: per (n,h) scores. Q and K arrive as 2 k-halves; sum while staging.
//   task<5 : A[nh][e][q] = sum_d mem[e,h,d] * Q[n,q,h,d]   (e-tile of 64)
//   task=5 : B[nh][k][q] = sum_d K[k,h,d]  * Q[n,q,h,d]
// ---------------------------------------------------------------------------
__global__ __launch_bounds__(256) void scores_kernel(
    const float* __restrict__ mem, const float* __restrict__ Q,
    const float* __restrict__ K, float* __restrict__ A, float* __restrict__ B)
{
    const int nh = blockIdx.x;          // 0..63
    const int n = nh >> 4, h = nh & 15;
    const int task = blockIdx.y;        // 0..4 = A e-tiles, 5 = B

    __shared__ float Ls[48][68];        // [d][r] (272B rows, float4-safe)
    __shared__ float Qs[48][68];        // [d][q]

    const int tid = threadIdx.x;
    const int r = tid >> 2;             // 0..63
    const int c = tid & 3;

    {
        const float* srcQ0 = Q + (size_t)(n * QL + r) * DD + h * HD;
        const float* srcQ1 = srcQ0 + (size_t)NN * QL * DD;
#pragma unroll
        for (int j = 0; j < 3; j++) {
            const int d0 = c * 4 + j * 16;
            const float4 q0 = *(const float4*)(srcQ0 + d0);
            const float4 q1 = *(const float4*)(srcQ1 + d0);
            Qs[d0 + 0][r] = q0.x + q1.x; Qs[d0 + 1][r] = q0.y + q1.y;
            Qs[d0 + 2][r] = q0.z + q1.z; Qs[d0 + 3][r] = q0.w + q1.w;
        }
        if (task < 5) {
            const int R = min(64, EE - task * 64);
            const float* srcL = mem + (size_t)(task * 64 + r) * DD + h * HD;
#pragma unroll
            for (int j = 0; j < 3; j++) {
                const int d0 = c * 4 + j * 16;
                float4 vl = make_float4(0.f, 0.f, 0.f, 0.f);
                if (r < R) vl = *(const float4*)(srcL + d0);
                Ls[d0 + 0][r] = vl.x; Ls[d0 + 1][r] = vl.y;
                Ls[d0 + 2][r] = vl.z; Ls[d0 + 3][r] = vl.w;
            }
        } else {
            const float* srcK0 = K + (size_t)r * DD + h * HD;
            const float* srcK1 = srcK0 + (size_t)KL * DD;
#pragma unroll
            for (int j = 0; j < 3; j++) {
                const int d0 = c * 4 + j * 16;
                const float4 k0v = *(const float4*)(srcK0 + d0);
                const float4 k1v = *(const float4*)(srcK1 + d0);
                Ls[d0 + 0][r] = k0v.x + k1v.x; Ls[d0 + 1][r] = k0v.y + k1v.y;
                Ls[d0 + 2][r] = k0v.z + k1v.z; Ls[d0 + 3][r] = k0v.w + k1v.w;
            }
        }
    }
    __syncthreads();

    const int tx = tid & 15, ty = tid >> 4;
    // accp[i][jp]: i = L-row of microtile, jp = q col pair (cols 2jp,2jp+1)
    ull accp[4][2];
#pragma unroll
    for (int i = 0; i < 4; i++) { accp[i][0] = 0ull; accp[i][1] = 0ull; }

#pragma unroll 8
    for (int d = 0; d < 48; d++) {
        const float4 a = *(const float4*)&Ls[d][ty * 4];
        const float4 b = *(const float4*)&Qs[d][tx * 4];
        const ull b01 = ((const ull*)&b)[0];
        const ull b23 = ((const ull*)&b)[1];
        ull ax2, ay2, az2, aw2;
        PK2(ax2, a.x, a.x); PK2(ay2, a.y, a.y);
        PK2(az2, a.z, a.z); PK2(aw2, a.w, a.w);
        FFMA2(accp[0][0], b01, ax2, accp[0][0]); FFMA2(accp[0][1], b23, ax2, accp[0][1]);
        FFMA2(accp[1][0], b01, ay2, accp[1][0]); FFMA2(accp[1][1], b23, ay2, accp[1][1]);
        FFMA2(accp[2][0], b01, az2, accp[2][0]); FFMA2(accp[2][1], b23, az2, accp[2][1]);
        FFMA2(accp[3][0], b01, aw2, accp[3][0]); FFMA2(accp[3][1], b23, aw2, accp[3][1]);
    }

    if (task < 5) {
        float* out = A + (size_t)nh * EE * QL;
#pragma unroll
        for (int i = 0; i < 4; i++) {
            int e = task * 64 + ty * 4 + i;
            if (e < EE) {
                float4 o;
                UPK2(o.x, o.y, accp[i][0]); UPK2(o.z, o.w, accp[i][1]);
                *(float4*)(out + (size_t)e * QL + tx * 4) = o;
            }
        }
    } else {
        float* out = B + (size_t)nh * KL * QL;
#pragma unroll
        for (int i = 0; i < 4; i++) {
            float4 o;
            UPK2(o.x, o.y, accp[i][0]); UPK2(o.z, o.w, accp[i][1]);
            *(float4*)(out + (size_t)(ty * 4 + i) * QL + tx * 4) = o;
        }
    }
}

// ---------------------------------------------------------------------------
// Kernel 3 (FUSED tsum+wk, f32x2): one 64-e tile per block.
//   pass1: Tsh[e][k] = sum_q relu(A[e,q]+B[k,q]) (k local 0..31)
//   pass2: w[k,q] += relu(A[e,q]+B[k,q]) * Tsh[e][k]
// grid (64 nh, 2 k-halves of 32, 5 e-chunks of 64), 256 threads.
// ---------------------------------------------------------------------------
__global__ __launch_bounds__(256) void wkfused_kernel(
    const float* __restrict__ A, const float* __restrict__ B,
    float* __restrict__ Wp)
{
    const int nh = blockIdx.x;
    const int kg = blockIdx.y;          // 0,1
    const int es = blockIdx.z;          // 0..4
    const int e0 = es * 64;
    const int ec = min(64, EE - e0);    // 64,64,64,64,44

    __shared__ float Ash[64][64];       // [e][q] (256B rows, float4-safe)
    __shared__ float Bsh[32][66];       // [k-local][q] (264B rows, ull-safe)
    __shared__ float Tsh[64][32];       // [e][k-local] (128B rows)

    const int tid = threadIdx.x;
    const int qx = tid & 15;            // pass2: q4 = qx*4
    const int ky = tid >> 4;            // pass2: local k pair = ky*2, ky*2+1
    const int kp = tid & 31;            // pass1: local k
    const int eb = tid >> 5;            // pass1: warp -> e group of 8

    const float* Bb = B + ((size_t)nh * KL + kg * 32) * QL;

    // load Bsh (32 x 64)
#pragma unroll
    for (int i = 0; i < 2; i++) {
        int f = tid + i * 256;
        int k = f >> 4, qq = (f & 15) * 4;
        float4 v = *(const float4*)(Bb + (size_t)k * QL + qq);
        Bsh[k][qq + 0] = v.x; Bsh[k][qq + 1] = v.y;
        Bsh[k][qq + 2] = v.z; Bsh[k][qq + 3] = v.w;
    }

    // pass2 per-thread B registers (as packed pairs)
    const float4 b0 = *(const float4*)(Bb + (size_t)(ky * 2) * QL + qx * 4);
    const float4 b1 = *(const float4*)(Bb + (size_t)(ky * 2 + 1) * QL + qx * 4);
    const ull b0a = ((const ull*)&b0)[0], b0b = ((const ull*)&b0)[1];
    const ull b1a = ((const ull*)&b1)[0], b1b = ((const ull*)&b1)[1];

    ull w0a = 0ull, w0b = 0ull, w1a = 0ull, w1b = 0ull;

    const float* Ab = A + (size_t)nh * EE * QL;

    // load A tile: 4 float4/thread (zero-pad beyond ec)
#pragma unroll
    for (int i = 0; i < 4; i++) {
        int f = tid + i * 256;
        int e = f >> 4, qq = (f & 15) * 4;
        float4 v = make_float4(0.f, 0.f, 0.f, 0.f);
        if (e < ec) v = *(const float4*)(Ab + (size_t)(e0 + e) * QL + qq);
        *(float4*)&Ash[e][qq] = v;
    }
    __syncthreads();

    // pass1: each thread sums 8 e rows (e = eb*8 + i) over all 64 q (packed q pairs)
    {
        ull tacc2[8];
#pragma unroll
        for (int i = 0; i < 8; i++) tacc2[i] = 0ull;
#pragma unroll 4
        for (int q2 = 0; q2 < 32; q2++) {
            const ull b2 = *(const ull*)&Bsh[kp][q2 * 2];
#pragma unroll
            for (int i = 0; i < 8; i++) {
                const ull a2 = *(const ull*)&Ash[eb * 8 + i][q2 * 2];
                ull p; FADD2(p, a2, b2);
                p = relu2(p);
                FADD2(tacc2[i], tacc2[i], p);
            }
        }
#pragma unroll
        for (int i = 0; i < 8; i++) {
            const int e = eb * 8 + i;
            float x, y; UPK2(x, y, tacc2[i]);
            Tsh[e][kp] = (e < ec) ? (x + y) : 0.f;  // zero padded rows
        }
    }
    __syncthreads();

    // pass2: microtile accumulate (packed)
#pragma unroll 8
    for (int e = 0; e < 64; e++) {
        const float4 a = *(const float4*)&Ash[e][qx * 4];
        const ull a01 = ((const ull*)&a)[0];
        const ull a23 = ((const ull*)&a)[1];
        const float2 t = *(const float2*)&Tsh[e][ky * 2];
        ull tx2, ty2; PK2(tx2, t.x, t.x); PK2(ty2, t.y, t.y);
        ull p;
        FADD2(p, a01, b0a); p = relu2(p); FFMA2(w0a, p, tx2, w0a);
        FADD2(p, a23, b0b); p = relu2(p); FFMA2(w0b, p, tx2, w0b);
        FADD2(p, a01, b1a); p = relu2(p); FFMA2(w1a, p, ty2, w1a);
        FADD2(p, a23, b1b); p = relu2(p); FFMA2(w1b, p, ty2, w1b);
    }

    float4 w0, w1;
    UPK2(w0.x, w0.y, w0a); UPK2(w0.z, w0.w, w0b);
    UPK2(w1.x, w1.y, w1a); UPK2(w1.z, w1.w, w1b);

    float* Wb = Wp + ((size_t)es * NH + nh) * KL * QL + (size_t)kg * 32 * QL;
    *(float4*)(Wb + (size_t)(ky * 2) * QL + qx * 4)     = w0;
    *(float4*)(Wb + (size_t)(ky * 2 + 1) * QL + qx * 4) = w1;
}

// ---------------------------------------------------------------------------
// Kernel 4: out[n,q,h,d] = sum_k (sum_es Wp[es])[nh][k][q] * V[k,h,d]
// grid (64 nh, 4 q-quarters of 16), 256 threads. V arrives as 2 halves.
// ---------------------------------------------------------------------------
__global__ __launch_bounds__(256) void out_kernel(
    const float* __restrict__ Wp, const float* __restrict__ V, float* __restrict__ out)
{
    const int nh = blockIdx.x;
    const int qy = blockIdx.y;          // q quarter
    const int n = nh >> 4, h = nh & 15;
    const int q0 = qy * 16;

    __shared__ float Ws[64][16];   // [k][q-local] (64B rows, float4-safe)
    __shared__ float Vs[64][48];   // [k][d] (192B rows, float4-safe)

    const int tid = threadIdx.x;
    const float* Wb = Wp + (size_t)nh * KL * QL + q0;

    // Ws: 1024 floats = 1 float4/thread, summing ESPLIT partials
    {
        int k = tid >> 2, qq = (tid & 3) * 4;
        const float* p = Wb + (size_t)k * QL + qq;
        float4 s = make_float4(0.f, 0.f, 0.f, 0.f);
#pragma unroll
        for (int es = 0; es < ESPLIT; es++) {
            const float4 v = *(const float4*)(p + (size_t)es * NH * KL * QL);
            s.x += v.x; s.y += v.y; s.z += v.z; s.w += v.w;
        }
        *(float4*)&Ws[k][qq] = s;
    }
    // Vs: 3072 floats = 3 float4/thread, summing 2 k-halves
#pragma unroll
    for (int i = 0; i < 3; i++) {
        int f = tid + i * 256;
        int k = f / 12, d4 = (f % 12) * 4;
        const float* p0 = V + (size_t)k * DD + h * HD + d4;
        const float4 v0 = *(const float4*)p0;
        const float4 v1 = *(const float4*)(p0 + (size_t)KL * DD);
        float4 s = make_float4(v0.x + v1.x, v0.y + v1.y, v0.z + v1.z, v0.w + v1.w);
        *(float4*)&Vs[k][d4] = s;
    }
    __syncthreads();

    const int tx = tid & 15;      // d group of 3
    const int ty = tid >> 4;      // q local (1 each)
    float acc[3] = {0.f, 0.f, 0.f};

#pragma unroll 8
    for (int kk = 0; kk < 64; kk++) {
        const float wq = Ws[kk][ty];
        acc[0] = fmaf(wq, Vs[kk][tx * 3 + 0], acc[0]);
        acc[1] = fmaf(wq, Vs[kk][tx * 3 + 1], acc[1]);
        acc[2] = fmaf(wq, Vs[kk][tx * 3 + 2], acc[2]);
    }

    const int q = q0 + ty;
#pragma unroll
    for (int j = 0; j < 3; j++)
        out[(size_t)(n * QL + q) * DD + h * HD + tx * 3 + j] = acc[j];
}

// ---------------------------------------------------------------------------
// Launch
// Inputs: 0=q 1=k 2=v 3=Wq 4=bq 5=Wk 6=bk 7=Wv 8=bv 9=memory
// ---------------------------------------------------------------------------
extern "C" void kernel_launch(void* const* d_in, const int* in_sizes, int n_in,
                              void* d_out, int out_size)
{
    const float* q   = (const float*)d_in[0];
    const float* k   = (const float*)d_in[1];
    const float* v   = (const float*)d_in[2];
    const float* Wq  = (const float*)d_in[3];
    const float* bq  = (const float*)d_in[4];
    const float* Wk  = (const float*)d_in[5];
    const float* bk  = (const float*)d_in[6];
    const float* Wv  = (const float*)d_in[7];
    const float* bv  = (const float*)d_in[8];
    const float* mem = (const float*)d_in[9];
    float* out = (float*)d_out;

    float *gQ, *gK, *gV, *gA, *gB, *gWp;
    cudaGetSymbolAddress((void**)&gQ, g_Q);
    cudaGetSymbolAddress((void**)&gK, g_K);
    cudaGetSymbolAddress((void**)&gV, g_V);
    cudaGetSymbolAddress((void**)&gA, g_A);
    cudaGetSymbolAddress((void**)&gB, g_B);
    cudaGetSymbolAddress((void**)&gWp, g_Wp);

    // 1. Fused projections, k-split x2 (288 blocks)
    proj_kernel<<<dim3(6, 24, 2), 256>>>(q, k, v, Wq, Wk, Wv, bq, bk, bv, gQ, gK, gV);

    // 2. A (mem·Q) and B (K·Q) scores (consumers sum the k-halves)
    scores_kernel<<<dim3(NH, 6), 256>>>(mem, gQ, gK, gA, gB);

    // 3. Fused T+W partials over 5 e-chunks (640 blocks)
    wkfused_kernel<<<dim3(NH, 2, ESPLIT), 256>>>(gA, gB, gWp);

    // 4. out = (sum of W partials)^T @ V_h (256 blocks)
    out_kernel<<<dim3(NH, 4), 256>>>(gWp, gV, out);
}